// round 1
// baseline (speedup 1.0000x reference)
#include <cuda_runtime.h>
#include <math.h>

#define BATCH   64
#define HIMG    28
#define WIMG    28
#define DIM     384
#define HEADS   12
#define HD      32
#define WIN     7
#define SHIFT   3
#define NTOK    49          // tokens per window
#define NWIN    16          // windows per image (4x4)
#define ROWS    (BATCH*NWIN*NTOK)   // 50176 total tokens
#define MLPH    1536

// ---------------- scratch (device globals; no allocation in kernel_launch) ----
__device__ float g_xw [ROWS*DIM];        // LN1 + shifted window-partitioned input
__device__ float g_qkv[ROWS*3*DIM];      // qkv projections
__device__ float g_att[ROWS*DIM];        // attention output (window order)
__device__ float g_x1 [ROWS*DIM];        // x + attn branch (image order)
__device__ float g_z  [ROWS*DIM];        // LN2 output
__device__ float g_hid[(size_t)ROWS*MLPH]; // fc1/gelu output

// ---------------- LayerNorm (optionally fused shift+window gather) -----------
// GATHER=1: output row r is window-ordered; source token computed via cyclic shift.
template<int GATHER>
__global__ void ln_kernel(const float* __restrict__ x, const float* __restrict__ w,
                          const float* __restrict__ b, float* __restrict__ out) {
    int r = blockIdx.x;
    int src = r;
    if (GATHER) {
        int bb  = r / (NWIN*NTOK);
        int rem = r % (NWIN*NTOK);
        int win = rem / NTOK, n = rem % NTOK;
        int wh = win / 4, ww = win % 4;
        int i = n / 7, j = n % 7;
        int sh = (wh*7 + i + SHIFT) % HIMG;
        int sw = (ww*7 + j + SHIFT) % WIMG;
        src = bb*(HIMG*WIMG) + sh*WIMG + sw;
    }
    const float* xp = x + (size_t)src * DIM;
    int tid = threadIdx.x;            // 128 threads, 3 elems each
    float v0 = xp[tid], v1 = xp[tid+128], v2 = xp[tid+256];
    float s = v0 + v1 + v2;
    __shared__ float red[4];
    #pragma unroll
    for (int o = 16; o; o >>= 1) s += __shfl_xor_sync(~0u, s, o);
    if ((tid & 31) == 0) red[tid >> 5] = s;
    __syncthreads();
    float mean = (red[0]+red[1]+red[2]+red[3]) * (1.0f/DIM);
    float d0 = v0-mean, d1 = v1-mean, d2 = v2-mean;
    float q = d0*d0 + d1*d1 + d2*d2;
    #pragma unroll
    for (int o = 16; o; o >>= 1) q += __shfl_xor_sync(~0u, q, o);
    __syncthreads();
    if ((tid & 31) == 0) red[tid >> 5] = q;
    __syncthreads();
    float var = (red[0]+red[1]+red[2]+red[3]) * (1.0f/DIM);
    float inv = rsqrtf(var + 1e-5f);
    float* op = out + (size_t)r * DIM;
    op[tid]     = d0*inv*w[tid]     + b[tid];
    op[tid+128] = d1*inv*w[tid+128] + b[tid+128];
    op[tid+256] = d2*inv*w[tid+256] + b[tid+256];
}

// ---------------- SGEMM: C[M,N] = A[M,K] @ W[N,K]^T, fused epilogues ----------
// MODE 0: + bias                      -> out[m][n]
// MODE 1: gelu(+ bias)                -> out[m][n]
// MODE 2: + bias + res[m][n]          -> out[m][n]
// MODE 3: + bias + res[dst] (scatter) -> out[dst]   (window-reverse + unshift)
#define BM 64
#define BN 64
#define BK 16
template<int MODE>
__global__ void gemm_kernel(const float* __restrict__ A, const float* __restrict__ W,
                            const float* __restrict__ bias, const float* __restrict__ res,
                            float* __restrict__ out, int M, int N, int K) {
    __shared__ __align__(16) float As[BK*BM];
    __shared__ __align__(16) float Bs[BK*BN];
    int tid = threadIdx.x;                 // 256 threads
    int tx = tid & 15, ty = tid >> 4;
    int m0 = blockIdx.y * BM, n0 = blockIdx.x * BN;
    float acc[4][4] = {};
    int lr = tid >> 2;                     // load row 0..63
    int lc = (tid & 3) * 4;                // k-offset within tile
    const float* Ap = A + (size_t)(m0 + lr) * K + lc;
    const float* Wp = W + (size_t)(n0 + lr) * K + lc;
    for (int kk = 0; kk < K; kk += BK) {
        float4 av = *(const float4*)(Ap + kk);
        float4 wv = *(const float4*)(Wp + kk);
        As[(lc+0)*BM + lr] = av.x; As[(lc+1)*BM + lr] = av.y;
        As[(lc+2)*BM + lr] = av.z; As[(lc+3)*BM + lr] = av.w;
        Bs[(lc+0)*BN + lr] = wv.x; Bs[(lc+1)*BN + lr] = wv.y;
        Bs[(lc+2)*BN + lr] = wv.z; Bs[(lc+3)*BN + lr] = wv.w;
        __syncthreads();
        #pragma unroll
        for (int k = 0; k < BK; k++) {
            float4 a  = *(const float4*)&As[k*BM + ty*4];
            float4 bv = *(const float4*)&Bs[k*BN + tx*4];
            float ar[4] = {a.x, a.y, a.z, a.w};
            float br[4] = {bv.x, bv.y, bv.z, bv.w};
            #pragma unroll
            for (int i = 0; i < 4; i++)
                #pragma unroll
                for (int j = 0; j < 4; j++)
                    acc[i][j] += ar[i] * br[j];
        }
        __syncthreads();
    }
    float4 bb = *(const float4*)&bias[n0 + tx*4];
    float br[4] = {bb.x, bb.y, bb.z, bb.w};
    #pragma unroll
    for (int i = 0; i < 4; i++) {
        int m = m0 + ty*4 + i;
        float v[4];
        #pragma unroll
        for (int j = 0; j < 4; j++) v[j] = acc[i][j] + br[j];
        if (MODE == 1) {
            #pragma unroll
            for (int j = 0; j < 4; j++)
                v[j] = 0.5f * v[j] * (1.0f + erff(v[j] * 0.70710678118654752f));
        }
        size_t dst;
        if (MODE == 3) {
            int bbi = m / (NWIN*NTOK);
            int rem = m % (NWIN*NTOK);
            int win = rem / NTOK, n = rem % NTOK;
            int wh = win/4, ww = win%4, ii = n/7, jj = n%7;
            int dh = (wh*7 + ii + SHIFT) % HIMG;
            int dw = (ww*7 + jj + SHIFT) % WIMG;
            dst = ((size_t)bbi*(HIMG*WIMG) + dh*WIMG + dw) * N + n0 + tx*4;
        } else {
            dst = (size_t)m * N + n0 + tx*4;
        }
        if (MODE == 2 || MODE == 3) {
            float4 rv = *(const float4*)&res[dst];
            v[0] += rv.x; v[1] += rv.y; v[2] += rv.z; v[3] += rv.w;
        }
        float4 o; o.x = v[0]; o.y = v[1]; o.z = v[2]; o.w = v[3];
        *(float4*)&out[dst] = o;
    }
}

// ---------------- windowed attention: one block per (window-batch, head) -----
__global__ void attn_kernel(const float* __restrict__ qkv,
                            const float* __restrict__ bias_table,
                            float* __restrict__ out) {
    int bw = blockIdx.x;      // 0..1023
    int h  = blockIdx.y;      // 0..11
    __shared__ float q[NTOK*HD], k[NTOK*HD], v[NTOK*HD];
    __shared__ float s[NTOK*52];
    int tid = threadIdx.x;    // 128
    const float scale = 0.17677669529663689f;   // 32^-0.5
    for (int idx = tid; idx < NTOK*HD; idx += 128) {
        int n = idx >> 5, d = idx & 31;
        size_t base = (size_t)(bw*NTOK + n) * (3*DIM) + h*HD + d;
        q[idx] = qkv[base] * scale;
        k[idx] = qkv[base + DIM];
        v[idx] = qkv[base + 2*DIM];
    }
    __syncthreads();
    int wh = (bw % NWIN) / 4, ww = bw % 4;
    for (int e = tid; e < NTOK*NTOK; e += 128) {
        int n = e / NTOK, m = e % NTOK;
        float dot = 0.f;
        #pragma unroll
        for (int d = 0; d < HD; d++) dot += q[n*HD+d] * k[m*HD+d];
        int i1 = n/7, j1 = n%7, i2 = m/7, j2 = m%7;
        int rel = (i1 - i2 + 6) * 13 + (j1 - j2 + 6);
        dot += bias_table[rel*HEADS + h];
        // region mask (shifted-window): regions at [0,21),[21,25),[25,28)
        int g1h = wh*7 + i1, g1w = ww*7 + j1;
        int g2h = wh*7 + i2, g2w = ww*7 + j2;
        int r1 = (g1h < 21 ? 0 : (g1h < 25 ? 1 : 2)) * 3 + (g1w < 21 ? 0 : (g1w < 25 ? 1 : 2));
        int r2 = (g2h < 21 ? 0 : (g2h < 25 ? 1 : 2)) * 3 + (g2w < 21 ? 0 : (g2w < 25 ? 1 : 2));
        if (r1 != r2) dot -= 100.f;
        s[n*52 + m] = dot;
    }
    __syncthreads();
    if (tid < NTOK) {
        float mx = -1e30f;
        #pragma unroll
        for (int m = 0; m < NTOK; m++) mx = fmaxf(mx, s[tid*52 + m]);
        float sum = 0.f;
        #pragma unroll
        for (int m = 0; m < NTOK; m++) { float e = __expf(s[tid*52+m] - mx); s[tid*52+m] = e; sum += e; }
        float inv = 1.f / sum;
        #pragma unroll
        for (int m = 0; m < NTOK; m++) s[tid*52 + m] *= inv;
    }
    __syncthreads();
    for (int idx = tid; idx < NTOK*HD; idx += 128) {
        int n = idx >> 5, d = idx & 31;
        float o = 0.f;
        #pragma unroll
        for (int m = 0; m < NTOK; m++) o += s[n*52 + m] * v[m*HD + d];
        out[(size_t)(bw*NTOK + n) * DIM + h*HD + d] = o;
    }
}

// ---------------- launcher ----------------------------------------------------
extern "C" void kernel_launch(void* const* d_in, const int* in_sizes, int n_in,
                              void* d_out, int out_size) {
    const float* x      = (const float*)d_in[0];
    const float* n1w    = (const float*)d_in[1];
    const float* n1b    = (const float*)d_in[2];
    const float* qkv_w  = (const float*)d_in[3];
    const float* qkv_b  = (const float*)d_in[4];
    const float* proj_w = (const float*)d_in[5];
    const float* proj_b = (const float*)d_in[6];
    const float* btab   = (const float*)d_in[7];
    const float* n2w    = (const float*)d_in[8];
    const float* n2b    = (const float*)d_in[9];
    const float* fc1_w  = (const float*)d_in[10];
    const float* fc1_b  = (const float*)d_in[11];
    const float* fc2_w  = (const float*)d_in[12];
    const float* fc2_b  = (const float*)d_in[13];
    float* out = (float*)d_out;

    float *xw, *qkvb, *att, *x1, *z, *hid;
    cudaGetSymbolAddress((void**)&xw,   g_xw);
    cudaGetSymbolAddress((void**)&qkvb, g_qkv);
    cudaGetSymbolAddress((void**)&att,  g_att);
    cudaGetSymbolAddress((void**)&x1,   g_x1);
    cudaGetSymbolAddress((void**)&z,    g_z);
    cudaGetSymbolAddress((void**)&hid,  g_hid);

    // 1. LN1 + cyclic shift + window partition
    ln_kernel<1><<<ROWS, 128>>>(x, n1w, n1b, xw);
    // 2. QKV projection
    gemm_kernel<0><<<dim3((3*DIM)/BN, ROWS/BM), 256>>>(xw, qkv_w, qkv_b, nullptr, qkvb, ROWS, 3*DIM, DIM);
    // 3. windowed attention (bias + mask computed analytically)
    attn_kernel<<<dim3(BATCH*NWIN, HEADS), 128>>>(qkvb, btab, att);
    // 4. output projection + window reverse + unshift + shortcut residual
    gemm_kernel<3><<<dim3(DIM/BN, ROWS/BM), 256>>>(att, proj_w, proj_b, x, x1, ROWS, DIM, DIM);
    // 5. LN2
    ln_kernel<0><<<ROWS, 128>>>(x1, n2w, n2b, z);
    // 6. fc1 + exact GELU
    gemm_kernel<1><<<dim3(MLPH/BN, ROWS/BM), 256>>>(z, fc1_w, fc1_b, nullptr, hid, ROWS, MLPH, DIM);
    // 7. fc2 + residual -> final output
    gemm_kernel<2><<<dim3(DIM/BN, ROWS/BM), 256>>>(hid, fc2_w, fc2_b, x1, out, ROWS, DIM, MLPH);
}

// round 3
// speedup vs baseline: 2.7281x; 2.7281x over previous
#include <cuda_runtime.h>
#include <math.h>
#include <stdint.h>

#define BATCH   64
#define HIMG    28
#define WIMG    28
#define DIM     384
#define HEADS   12
#define HD      32
#define WIN     7
#define SHIFT   3
#define NTOK    49
#define NWIN    16
#define ROWS    (BATCH*NWIN*NTOK)   // 50176
#define MLPH    1536

// ---------------- scratch ----------------------------------------------------
__device__ float g_xw [ROWS*DIM];
__device__ float g_qkv[ROWS*3*DIM];
__device__ float g_att[ROWS*DIM];
__device__ float g_x1 [ROWS*DIM];
__device__ float g_z  [ROWS*DIM];
__device__ float g_hid[(size_t)ROWS*MLPH];

// ---------------- helpers ------------------------------------------------------
__device__ __forceinline__ uint32_t f2tf32(float x) {
    uint32_t r;
    asm("cvt.rna.tf32.f32 %0, %1;" : "=r"(r) : "f"(x));
    return r;
}
__device__ __forceinline__ void mma_tf32(float* d, const uint32_t* a, const uint32_t* b) {
    asm volatile(
        "mma.sync.aligned.m16n8k8.row.col.f32.tf32.tf32.f32 "
        "{%0,%1,%2,%3}, {%4,%5,%6,%7}, {%8,%9}, {%0,%1,%2,%3};"
        : "+f"(d[0]), "+f"(d[1]), "+f"(d[2]), "+f"(d[3])
        : "r"(a[0]), "r"(a[1]), "r"(a[2]), "r"(a[3]), "r"(b[0]), "r"(b[1]));
}

// ---------------- LayerNorm (optionally fused shift+window gather) -----------
template<int GATHER>
__global__ void ln_kernel(const float* __restrict__ x, const float* __restrict__ w,
                          const float* __restrict__ b, float* __restrict__ out) {
    int r = blockIdx.x;
    int src = r;
    if (GATHER) {
        int bb  = r / (NWIN*NTOK);
        int rem = r % (NWIN*NTOK);
        int win = rem / NTOK, n = rem % NTOK;
        int wh = win / 4, ww = win % 4;
        int i = n / 7, j = n % 7;
        int sh = (wh*7 + i + SHIFT) % HIMG;
        int sw = (ww*7 + j + SHIFT) % WIMG;
        src = bb*(HIMG*WIMG) + sh*WIMG + sw;
    }
    const float* xp = x + (size_t)src * DIM;
    int tid = threadIdx.x;
    float v0 = xp[tid], v1 = xp[tid+128], v2 = xp[tid+256];
    float s = v0 + v1 + v2;
    __shared__ float red[4];
    #pragma unroll
    for (int o = 16; o; o >>= 1) s += __shfl_xor_sync(~0u, s, o);
    if ((tid & 31) == 0) red[tid >> 5] = s;
    __syncthreads();
    float mean = (red[0]+red[1]+red[2]+red[3]) * (1.0f/DIM);
    float d0 = v0-mean, d1 = v1-mean, d2 = v2-mean;
    float q = d0*d0 + d1*d1 + d2*d2;
    #pragma unroll
    for (int o = 16; o; o >>= 1) q += __shfl_xor_sync(~0u, q, o);
    __syncthreads();
    if ((tid & 31) == 0) red[tid >> 5] = q;
    __syncthreads();
    float var = (red[0]+red[1]+red[2]+red[3]) * (1.0f/DIM);
    float inv = rsqrtf(var + 1e-5f);
    float* op = out + (size_t)r * DIM;
    op[tid]     = d0*inv*w[tid]     + b[tid];
    op[tid+128] = d1*inv*w[tid+128] + b[tid+128];
    op[tid+256] = d2*inv*w[tid+256] + b[tid+256];
}

// ---------------- tf32 tensor-core GEMM: C[M,N] = A[M,K] @ W[N,K]^T ----------
// 128x128x32 CTA tile, 8 warps (2x4), warp tile 64x32 (4x4 m16n8k8).
// SMEM layout: As[m][k ^ ((m&7)*4)], Bs[n][k ^ ((n&7)*4)]  (conflict-free)
// MODE 0: +bias | 1: gelu(+bias) | 2: +bias+res | 3: +bias+res, scatter rows
template<int MODE>
__global__ void __launch_bounds__(256, 2)
mma_gemm(const float* __restrict__ A, const float* __restrict__ W,
         const float* __restrict__ bias, const float* __restrict__ res,
         float* __restrict__ out, int M, int N, int K) {
    __shared__ __align__(16) uint32_t As[128*32];
    __shared__ __align__(16) uint32_t Bs[128*32];
    int tid  = threadIdx.x;
    int wid  = tid >> 5, lane = tid & 31;
    int wm   = wid >> 2, wn = wid & 3;           // warp grid 2x4
    int q    = lane >> 2, c = lane & 3;          // quad row / thread-in-quad
    int m0   = blockIdx.y * 128, n0 = blockIdx.x * 128;

    // per-thread staging coords: lanes along k for coalescing
    int sm = tid >> 3;          // 0..31 row base (×4 iters -> 128)
    int sc4 = tid & 7;          // float4 index along k (8 per 32-float row)

    float acc[4][4][4];
    #pragma unroll
    for (int i = 0; i < 4; i++)
        #pragma unroll
        for (int j = 0; j < 4; j++)
            #pragma unroll
            for (int e = 0; e < 4; e++) acc[i][j][e] = 0.f;

    const int swz = q * 4;

    for (int kk = 0; kk < K; kk += 32) {
        // ---- stage A and B tiles (tf32-converted, swizzled) ----
        #pragma unroll
        for (int i = 0; i < 4; i++) {
            int m = sm + i*32;
            uint32_t col = (uint32_t)((sc4*4) ^ ((m & 7) * 4));
            float4 av = *(const float4*)(A + (size_t)(m0+m)*K + kk + sc4*4);
            uint4 at; at.x = f2tf32(av.x); at.y = f2tf32(av.y);
                      at.z = f2tf32(av.z); at.w = f2tf32(av.w);
            *(uint4*)&As[m*32 + col] = at;
            float4 wv = *(const float4*)(W + (size_t)(n0+m)*K + kk + sc4*4);
            uint4 wt; wt.x = f2tf32(wv.x); wt.y = f2tf32(wv.y);
                      wt.z = f2tf32(wv.z); wt.w = f2tf32(wv.w);
            *(uint4*)&Bs[m*32 + col] = wt;
        }
        __syncthreads();

        // ---- 4 k-steps of m16n8k8 ----
        #pragma unroll
        for (int ks = 0; ks < 4; ks++) {
            int kb = ks * 8;
            int c0 = (kb + c) ^ swz;
            int c1 = (kb + c + 4) ^ swz;
            uint32_t af[4][4];
            #pragma unroll
            for (int mi = 0; mi < 4; mi++) {
                int r0 = wm*64 + mi*16 + q;
                af[mi][0] = As[r0*32 + c0];
                af[mi][1] = As[(r0+8)*32 + c0];
                af[mi][2] = As[r0*32 + c1];
                af[mi][3] = As[(r0+8)*32 + c1];
            }
            uint32_t bf[4][2];
            #pragma unroll
            for (int ni = 0; ni < 4; ni++) {
                int nr = wn*32 + ni*8 + q;
                bf[ni][0] = Bs[nr*32 + c0];
                bf[ni][1] = Bs[nr*32 + c1];
            }
            #pragma unroll
            for (int mi = 0; mi < 4; mi++)
                #pragma unroll
                for (int ni = 0; ni < 4; ni++)
                    mma_tf32(acc[mi][ni], af[mi], bf[ni]);
        }
        __syncthreads();
    }

    // ---- epilogue ----
    #pragma unroll
    for (int mi = 0; mi < 4; mi++) {
        int r0 = m0 + wm*64 + mi*16 + q;
        int r1 = r0 + 8;
        size_t or0, or1;
        if (MODE == 3) {
            #pragma unroll
            for (int half = 0; half < 2; half++) {
                int m = half ? r1 : r0;
                int bbi = m / (NWIN*NTOK);
                int rem = m % (NWIN*NTOK);
                int win = rem / NTOK, n = rem % NTOK;
                int wh = win >> 2, ww = win & 3, ii = n / 7, jj = n % 7;
                int dh = (wh*7 + ii + SHIFT) % HIMG;
                int dw = (ww*7 + jj + SHIFT) % WIMG;
                size_t o = (size_t)bbi*(HIMG*WIMG) + dh*WIMG + dw;
                if (half) or1 = o; else or0 = o;
            }
        } else {
            or0 = (size_t)r0; or1 = (size_t)r1;
        }
        #pragma unroll
        for (int ni = 0; ni < 4; ni++) {
            int col = n0 + wn*32 + ni*8 + 2*c;
            float2 bv = *(const float2*)&bias[col];
            float v00 = acc[mi][ni][0] + bv.x, v01 = acc[mi][ni][1] + bv.y;
            float v10 = acc[mi][ni][2] + bv.x, v11 = acc[mi][ni][3] + bv.y;
            if (MODE == 1) {
                v00 = 0.5f*v00*(1.0f + erff(v00*0.70710678118654752f));
                v01 = 0.5f*v01*(1.0f + erff(v01*0.70710678118654752f));
                v10 = 0.5f*v10*(1.0f + erff(v10*0.70710678118654752f));
                v11 = 0.5f*v11*(1.0f + erff(v11*0.70710678118654752f));
            }
            if (MODE >= 2) {
                float2 ra = *(const float2*)&res[or0*N + col];
                float2 rb = *(const float2*)&res[or1*N + col];
                v00 += ra.x; v01 += ra.y; v10 += rb.x; v11 += rb.y;
            }
            float2 o0; o0.x = v00; o0.y = v01;
            float2 o1; o1.x = v10; o1.y = v11;
            *(float2*)&out[or0*N + col] = o0;
            *(float2*)&out[or1*N + col] = o1;
        }
    }
}

// ---------------- windowed attention ------------------------------------------
__global__ void attn_kernel(const float* __restrict__ qkv,
                            const float* __restrict__ bias_table,
                            float* __restrict__ out) {
    int bw = blockIdx.x;
    int h  = blockIdx.y;
    __shared__ float q[NTOK*HD], k[NTOK*HD], v[NTOK*HD];
    __shared__ float s[NTOK*52];
    int tid = threadIdx.x;
    const float scale = 0.17677669529663689f;
    for (int idx = tid; idx < NTOK*HD; idx += 128) {
        int n = idx >> 5, d = idx & 31;
        size_t base = (size_t)(bw*NTOK + n) * (3*DIM) + h*HD + d;
        q[idx] = qkv[base] * scale;
        k[idx] = qkv[base + DIM];
        v[idx] = qkv[base + 2*DIM];
    }
    __syncthreads();
    int wh = (bw % NWIN) / 4, ww = bw % 4;
    for (int e = tid; e < NTOK*NTOK; e += 128) {
        int n = e / NTOK, m = e % NTOK;
        float dot = 0.f;
        #pragma unroll
        for (int d = 0; d < HD; d++) dot += q[n*HD+d] * k[m*HD+d];
        int i1 = n/7, j1 = n%7, i2 = m/7, j2 = m%7;
        int rel = (i1 - i2 + 6) * 13 + (j1 - j2 + 6);
        dot += bias_table[rel*HEADS + h];
        int g1h = wh*7 + i1, g1w = ww*7 + j1;
        int g2h = wh*7 + i2, g2w = ww*7 + j2;
        int r1 = (g1h < 21 ? 0 : (g1h < 25 ? 1 : 2)) * 3 + (g1w < 21 ? 0 : (g1w < 25 ? 1 : 2));
        int r2 = (g2h < 21 ? 0 : (g2h < 25 ? 1 : 2)) * 3 + (g2w < 21 ? 0 : (g2w < 25 ? 1 : 2));
        if (r1 != r2) dot -= 100.f;
        s[n*52 + m] = dot;
    }
    __syncthreads();
    if (tid < NTOK) {
        float mx = -1e30f;
        #pragma unroll
        for (int m = 0; m < NTOK; m++) mx = fmaxf(mx, s[tid*52 + m]);
        float sum = 0.f;
        #pragma unroll
        for (int m = 0; m < NTOK; m++) { float e = __expf(s[tid*52+m] - mx); s[tid*52+m] = e; sum += e; }
        float inv = 1.f / sum;
        #pragma unroll
        for (int m = 0; m < NTOK; m++) s[tid*52 + m] *= inv;
    }
    __syncthreads();
    for (int idx = tid; idx < NTOK*HD; idx += 128) {
        int n = idx >> 5, d = idx & 31;
        float o = 0.f;
        #pragma unroll
        for (int m = 0; m < NTOK; m++) o += s[n*52 + m] * v[m*HD + d];
        out[(size_t)(bw*NTOK + n) * DIM + h*HD + d] = o;
    }
}

// ---------------- launcher -----------------------------------------------------
extern "C" void kernel_launch(void* const* d_in, const int* in_sizes, int n_in,
                              void* d_out, int out_size) {
    const float* x      = (const float*)d_in[0];
    const float* n1w    = (const float*)d_in[1];
    const float* n1b    = (const float*)d_in[2];
    const float* qkv_w  = (const float*)d_in[3];
    const float* qkv_b  = (const float*)d_in[4];
    const float* proj_w = (const float*)d_in[5];
    const float* proj_b = (const float*)d_in[6];
    const float* btab   = (const float*)d_in[7];
    const float* n2w    = (const float*)d_in[8];
    const float* n2b    = (const float*)d_in[9];
    const float* fc1_w  = (const float*)d_in[10];
    const float* fc1_b  = (const float*)d_in[11];
    const float* fc2_w  = (const float*)d_in[12];
    const float* fc2_b  = (const float*)d_in[13];
    float* out = (float*)d_out;

    float *xw, *qkvb, *att, *x1, *z, *hid;
    cudaGetSymbolAddress((void**)&xw,   g_xw);
    cudaGetSymbolAddress((void**)&qkvb, g_qkv);
    cudaGetSymbolAddress((void**)&att,  g_att);
    cudaGetSymbolAddress((void**)&x1,   g_x1);
    cudaGetSymbolAddress((void**)&z,    g_z);
    cudaGetSymbolAddress((void**)&hid,  g_hid);

    // 1. LN1 + cyclic shift + window partition
    ln_kernel<1><<<ROWS, 128>>>(x, n1w, n1b, xw);
    // 2. QKV projection (tf32 tensor cores)
    mma_gemm<0><<<dim3((3*DIM)/128, ROWS/128), 256>>>(xw, qkv_w, qkv_b, nullptr, qkvb, ROWS, 3*DIM, DIM);
    // 3. windowed attention
    attn_kernel<<<dim3(BATCH*NWIN, HEADS), 128>>>(qkvb, btab, att);
    // 4. proj + window reverse + unshift + shortcut residual
    mma_gemm<3><<<dim3(DIM/128, ROWS/128), 256>>>(att, proj_w, proj_b, x, x1, ROWS, DIM, DIM);
    // 5. LN2
    ln_kernel<0><<<ROWS, 128>>>(x1, n2w, n2b, z);
    // 6. fc1 + exact GELU
    mma_gemm<1><<<dim3(MLPH/128, ROWS/128), 256>>>(z, fc1_w, fc1_b, nullptr, hid, ROWS, MLPH, DIM);
    // 7. fc2 + residual -> final output
    mma_gemm<2><<<dim3(DIM/128, ROWS/128), 256>>>(hid, fc2_w, fc2_b, x1, out, ROWS, DIM, MLPH);
}

// round 4
// speedup vs baseline: 4.2756x; 1.5672x over previous
#include <cuda_runtime.h>
#include <math.h>
#include <stdint.h>

#define BATCH   64
#define HIMG    28
#define WIMG    28
#define DIM     384
#define HEADS   12
#define HD      32
#define WIN     7
#define SHIFT   3
#define NTOK    49
#define NWIN    16
#define ROWS    (BATCH*NWIN*NTOK)   // 50176
#define MLPH    1536

// ---------------- scratch ----------------------------------------------------
__device__ float g_xw [ROWS*DIM];
__device__ float g_qkv[ROWS*3*DIM];
__device__ float g_att[ROWS*DIM];
__device__ float g_x1 [ROWS*DIM];
__device__ float g_z  [ROWS*DIM];
__device__ float g_hid[(size_t)ROWS*MLPH];
// tf32-rounded weights
__device__ float g_wq[3*DIM*DIM];
__device__ float g_wp[DIM*DIM];
__device__ float g_w1[MLPH*DIM];
__device__ float g_w2[DIM*MLPH];

// ---------------- helpers ------------------------------------------------------
__device__ __forceinline__ uint32_t f2tf32(float x) {
    uint32_t r;
    asm("cvt.rna.tf32.f32 %0, %1;" : "=r"(r) : "f"(x));
    return r;
}
__device__ __forceinline__ float tf32r(float x) { return __uint_as_float(f2tf32(x)); }

__device__ __forceinline__ uint32_t smem_u32(const void* p) {
    uint32_t a;
    asm("{ .reg .u64 t; cvta.to.shared.u64 t, %1; cvt.u32.u64 %0, t; }" : "=r"(a) : "l"(p));
    return a;
}
__device__ __forceinline__ void cp16(uint32_t s, const void* g) {
    asm volatile("cp.async.cg.shared.global [%0], [%1], 16;" :: "r"(s), "l"(g));
}
#define CP_COMMIT() asm volatile("cp.async.commit_group;" ::: "memory")
#define CP_WAIT1()  asm volatile("cp.async.wait_group 1;" ::: "memory")

__device__ __forceinline__ void mma_tf32(float* d, const uint32_t* a, const uint32_t* b) {
    asm volatile(
        "mma.sync.aligned.m16n8k8.row.col.f32.tf32.tf32.f32 "
        "{%0,%1,%2,%3}, {%4,%5,%6,%7}, {%8,%9}, {%0,%1,%2,%3};"
        : "+f"(d[0]), "+f"(d[1]), "+f"(d[2]), "+f"(d[3])
        : "r"(a[0]), "r"(a[1]), "r"(a[2]), "r"(a[3]), "r"(b[0]), "r"(b[1]));
}

// ---------------- weight prep: tf32-round copy ---------------------------------
__global__ void wprep_kernel(const float* __restrict__ src, float* __restrict__ dst, int n4) {
    int i = blockIdx.x * blockDim.x + threadIdx.x;
    if (i < n4) {
        float4 v = ((const float4*)src)[i];
        v.x = tf32r(v.x); v.y = tf32r(v.y); v.z = tf32r(v.z); v.w = tf32r(v.w);
        ((float4*)dst)[i] = v;
    }
}

// ---------------- LayerNorm (optionally fused shift+window gather) -----------
// outputs are tf32-rounded (they only feed GEMM A operands)
template<int GATHER>
__global__ void ln_kernel(const float* __restrict__ x, const float* __restrict__ w,
                          const float* __restrict__ b, float* __restrict__ out) {
    int r = blockIdx.x;
    int src = r;
    if (GATHER) {
        int bb  = r / (NWIN*NTOK);
        int rem = r % (NWIN*NTOK);
        int win = rem / NTOK, n = rem % NTOK;
        int wh = win / 4, ww = win % 4;
        int i = n / 7, j = n % 7;
        int sh = (wh*7 + i + SHIFT) % HIMG;
        int sw = (ww*7 + j + SHIFT) % WIMG;
        src = bb*(HIMG*WIMG) + sh*WIMG + sw;
    }
    const float* xp = x + (size_t)src * DIM;
    int tid = threadIdx.x;
    float v0 = xp[tid], v1 = xp[tid+128], v2 = xp[tid+256];
    float s = v0 + v1 + v2;
    __shared__ float red[4];
    #pragma unroll
    for (int o = 16; o; o >>= 1) s += __shfl_xor_sync(~0u, s, o);
    if ((tid & 31) == 0) red[tid >> 5] = s;
    __syncthreads();
    float mean = (red[0]+red[1]+red[2]+red[3]) * (1.0f/DIM);
    float d0 = v0-mean, d1 = v1-mean, d2 = v2-mean;
    float q = d0*d0 + d1*d1 + d2*d2;
    #pragma unroll
    for (int o = 16; o; o >>= 1) q += __shfl_xor_sync(~0u, q, o);
    __syncthreads();
    if ((tid & 31) == 0) red[tid >> 5] = q;
    __syncthreads();
    float var = (red[0]+red[1]+red[2]+red[3]) * (1.0f/DIM);
    float inv = rsqrtf(var + 1e-5f);
    float* op = out + (size_t)r * DIM;
    op[tid]     = tf32r(d0*inv*w[tid]     + b[tid]);
    op[tid+128] = tf32r(d1*inv*w[tid+128] + b[tid+128]);
    op[tid+256] = tf32r(d2*inv*w[tid+256] + b[tid+256]);
}

// ---------------- pipelined tf32 GEMM: C[M,N] = A[M,K] @ W[N,K]^T -------------
// 128x128x32 CTA tile, 3-stage cp.async, 8 warps (2x4), warp tile 64x32.
// Inputs must be pre-rounded to tf32 (raw bits fed to MMA).
// MODE 0: +bias | 1: gelu(+bias), tf32-round out | 2: +bias+res | 3: +bias+res scatter
#define SSZ 8192   // u32 per stage (A 4096 + B 4096)
template<int MODE>
__global__ void __launch_bounds__(256, 2)
mma_gemm(const float* __restrict__ A, const float* __restrict__ W,
         const float* __restrict__ bias, const float* __restrict__ res,
         float* __restrict__ out, int M, int N, int K) {
    extern __shared__ __align__(16) uint32_t smem[];
    uint32_t sbase = smem_u32(smem);
    int tid  = threadIdx.x;
    int wid  = tid >> 5, lane = tid & 31;
    int wm   = wid >> 2, wn = wid & 3;
    int q    = lane >> 2, c = lane & 3;
    int m0   = blockIdx.y * 128, n0 = blockIdx.x * 128;

    int sr = tid >> 3;          // 0..31 row base
    int sc = tid & 7;           // 16B chunk along k

    const float* Ag0 = A + (size_t)(m0 + sr) * K + sc*4;
    const float* Wg0 = W + (size_t)(n0 + sr) * K + sc*4;

    float acc[4][4][4];
    #pragma unroll
    for (int i = 0; i < 4; i++)
        #pragma unroll
        for (int j = 0; j < 4; j++)
            #pragma unroll
            for (int e = 0; e < 4; e++) acc[i][j][e] = 0.f;

    const int T = K >> 5;

    auto load_tile = [&](int t) {
        uint32_t sb = sbase + (uint32_t)(t % 3) * (SSZ*4);
        const float* Ag = Ag0 + t*32;
        const float* Wg = Wg0 + t*32;
        #pragma unroll
        for (int i = 0; i < 4; i++) {
            int m = sr + i*32;
            uint32_t off = (uint32_t)(m*128 + ((sc*16) ^ ((m & 7) * 16)));
            cp16(sb + off,         Ag + (size_t)i*32*K);
            cp16(sb + 16384 + off, Wg + (size_t)i*32*K);
        }
    };

    load_tile(0); CP_COMMIT();
    load_tile(1); CP_COMMIT();

    const int swz = q * 4;
    for (int t = 0; t < T; t++) {
        CP_WAIT1();
        __syncthreads();
        if (t + 2 < T) load_tile(t + 2);
        CP_COMMIT();

        const uint32_t* As = smem + (t % 3) * SSZ;
        const uint32_t* Bs = As + 4096;
        #pragma unroll
        for (int ks = 0; ks < 4; ks++) {
            int kb = ks * 8;
            int c0 = (kb + c) ^ swz;
            int c1 = (kb + c + 4) ^ swz;
            uint32_t af[4][4];
            #pragma unroll
            for (int mi = 0; mi < 4; mi++) {
                int r0 = wm*64 + mi*16 + q;
                af[mi][0] = As[r0*32 + c0];
                af[mi][1] = As[(r0+8)*32 + c0];
                af[mi][2] = As[r0*32 + c1];
                af[mi][3] = As[(r0+8)*32 + c1];
            }
            uint32_t bf[4][2];
            #pragma unroll
            for (int ni = 0; ni < 4; ni++) {
                int nr = wn*32 + ni*8 + q;
                bf[ni][0] = Bs[nr*32 + c0];
                bf[ni][1] = Bs[nr*32 + c1];
            }
            #pragma unroll
            for (int mi = 0; mi < 4; mi++)
                #pragma unroll
                for (int ni = 0; ni < 4; ni++)
                    mma_tf32(acc[mi][ni], af[mi], bf[ni]);
        }
        __syncthreads();
    }

    // ---- epilogue ----
    #pragma unroll
    for (int mi = 0; mi < 4; mi++) {
        int r0 = m0 + wm*64 + mi*16 + q;
        int r1 = r0 + 8;
        size_t or0, or1;
        if (MODE == 3) {
            #pragma unroll
            for (int half = 0; half < 2; half++) {
                int m = half ? r1 : r0;
                int bbi = m / (NWIN*NTOK);
                int rem = m % (NWIN*NTOK);
                int win = rem / NTOK, n = rem % NTOK;
                int wh = win >> 2, ww = win & 3, ii = n / 7, jj = n % 7;
                int dh = (wh*7 + ii + SHIFT) % HIMG;
                int dw = (ww*7 + jj + SHIFT) % WIMG;
                size_t o = (size_t)bbi*(HIMG*WIMG) + dh*WIMG + dw;
                if (half) or1 = o; else or0 = o;
            }
        } else {
            or0 = (size_t)r0; or1 = (size_t)r1;
        }
        #pragma unroll
        for (int ni = 0; ni < 4; ni++) {
            int col = n0 + wn*32 + ni*8 + 2*c;
            float2 bv = *(const float2*)&bias[col];
            float v00 = acc[mi][ni][0] + bv.x, v01 = acc[mi][ni][1] + bv.y;
            float v10 = acc[mi][ni][2] + bv.x, v11 = acc[mi][ni][3] + bv.y;
            if (MODE == 1) {
                v00 = tf32r(0.5f*v00*(1.0f + erff(v00*0.70710678118654752f)));
                v01 = tf32r(0.5f*v01*(1.0f + erff(v01*0.70710678118654752f)));
                v10 = tf32r(0.5f*v10*(1.0f + erff(v10*0.70710678118654752f)));
                v11 = tf32r(0.5f*v11*(1.0f + erff(v11*0.70710678118654752f)));
            }
            if (MODE >= 2) {
                float2 ra = *(const float2*)&res[or0*N + col];
                float2 rb = *(const float2*)&res[or1*N + col];
                v00 += ra.x; v01 += ra.y; v10 += rb.x; v11 += rb.y;
            }
            float2 o0; o0.x = v00; o0.y = v01;
            float2 o1; o1.x = v10; o1.y = v11;
            *(float2*)&out[or0*N + col] = o0;
            *(float2*)&out[or1*N + col] = o1;
        }
    }
}

// ---------------- windowed attention (bank-conflict-free smem) -----------------
#define QS 36
#define VS 33
#define SS 53
__global__ void attn_kernel(const float* __restrict__ qkv,
                            const float* __restrict__ bias_table,
                            float* __restrict__ out) {
    int bw = blockIdx.x;
    int h  = blockIdx.y;
    __shared__ float q[NTOK*QS], k[NTOK*QS], v[NTOK*VS];
    __shared__ float s[NTOK*SS];
    __shared__ float bsm[169];
    int tid = threadIdx.x;
    const float scale = 0.17677669529663689f;
    for (int idx = tid; idx < NTOK*HD; idx += 128) {
        int n = idx >> 5, d = idx & 31;
        size_t base = (size_t)(bw*NTOK + n) * (3*DIM) + h*HD + d;
        q[n*QS+d] = qkv[base] * scale;
        k[n*QS+d] = qkv[base + DIM];
        v[n*VS+d] = qkv[base + 2*DIM];
    }
    for (int i = tid; i < 169; i += 128) bsm[i] = bias_table[i*HEADS + h];
    __syncthreads();
    int wh = (bw % NWIN) / 4, ww = bw % 4;
    for (int e = tid; e < NTOK*NTOK; e += 128) {
        int n = e / NTOK, m = e % NTOK;
        float dot = 0.f;
        #pragma unroll
        for (int j = 0; j < 8; j++) {
            float4 aq = *(const float4*)&q[n*QS + 4*j];
            float4 ak = *(const float4*)&k[m*QS + 4*j];
            dot += aq.x*ak.x + aq.y*ak.y + aq.z*ak.z + aq.w*ak.w;
        }
        int i1 = n/7, j1 = n%7, i2 = m/7, j2 = m%7;
        dot += bsm[(i1 - i2 + 6) * 13 + (j1 - j2 + 6)];
        int g1h = wh*7 + i1, g1w = ww*7 + j1;
        int g2h = wh*7 + i2, g2w = ww*7 + j2;
        int r1 = (g1h < 21 ? 0 : (g1h < 25 ? 1 : 2)) * 3 + (g1w < 21 ? 0 : (g1w < 25 ? 1 : 2));
        int r2 = (g2h < 21 ? 0 : (g2h < 25 ? 1 : 2)) * 3 + (g2w < 21 ? 0 : (g2w < 25 ? 1 : 2));
        if (r1 != r2) dot -= 100.f;
        s[n*SS + m] = dot;
    }
    __syncthreads();
    if (tid < NTOK) {
        float mx = -1e30f;
        #pragma unroll
        for (int m = 0; m < NTOK; m++) mx = fmaxf(mx, s[tid*SS + m]);
        float sum = 0.f;
        #pragma unroll
        for (int m = 0; m < NTOK; m++) { float e = __expf(s[tid*SS+m] - mx); s[tid*SS+m] = e; sum += e; }
        float inv = 1.f / sum;
        #pragma unroll
        for (int m = 0; m < NTOK; m++) s[tid*SS + m] *= inv;
    }
    __syncthreads();
    for (int idx = tid; idx < NTOK*HD; idx += 128) {
        int n = idx >> 5, d = idx & 31;
        float o = 0.f;
        #pragma unroll
        for (int m = 0; m < NTOK; m++) o += s[n*SS + m] * v[m*VS + d];
        out[(size_t)(bw*NTOK + n) * DIM + h*HD + d] = tf32r(o);
    }
}

// ---------------- launcher -----------------------------------------------------
extern "C" void kernel_launch(void* const* d_in, const int* in_sizes, int n_in,
                              void* d_out, int out_size) {
    const float* x      = (const float*)d_in[0];
    const float* n1w    = (const float*)d_in[1];
    const float* n1b    = (const float*)d_in[2];
    const float* qkv_w  = (const float*)d_in[3];
    const float* qkv_b  = (const float*)d_in[4];
    const float* proj_w = (const float*)d_in[5];
    const float* proj_b = (const float*)d_in[6];
    const float* btab   = (const float*)d_in[7];
    const float* n2w    = (const float*)d_in[8];
    const float* n2b    = (const float*)d_in[9];
    const float* fc1_w  = (const float*)d_in[10];
    const float* fc1_b  = (const float*)d_in[11];
    const float* fc2_w  = (const float*)d_in[12];
    const float* fc2_b  = (const float*)d_in[13];
    float* out = (float*)d_out;

    float *xw, *qkvb, *att, *x1, *z, *hid, *wq, *wp, *w1, *w2;
    cudaGetSymbolAddress((void**)&xw,   g_xw);
    cudaGetSymbolAddress((void**)&qkvb, g_qkv);
    cudaGetSymbolAddress((void**)&att,  g_att);
    cudaGetSymbolAddress((void**)&x1,   g_x1);
    cudaGetSymbolAddress((void**)&z,    g_z);
    cudaGetSymbolAddress((void**)&hid,  g_hid);
    cudaGetSymbolAddress((void**)&wq,   g_wq);
    cudaGetSymbolAddress((void**)&wp,   g_wp);
    cudaGetSymbolAddress((void**)&w1,   g_w1);
    cudaGetSymbolAddress((void**)&w2,   g_w2);

    const int SMEM = 3 * SSZ * 4;   // 98304 bytes
    static bool attr_done = false;
    if (!attr_done) {
        cudaFuncSetAttribute(mma_gemm<0>, cudaFuncAttributeMaxDynamicSharedMemorySize, SMEM);
        cudaFuncSetAttribute(mma_gemm<1>, cudaFuncAttributeMaxDynamicSharedMemorySize, SMEM);
        cudaFuncSetAttribute(mma_gemm<2>, cudaFuncAttributeMaxDynamicSharedMemorySize, SMEM);
        cudaFuncSetAttribute(mma_gemm<3>, cudaFuncAttributeMaxDynamicSharedMemorySize, SMEM);
        attr_done = true;
    }

    // 0. tf32-round weights
    wprep_kernel<<<(3*DIM*DIM/4 + 255)/256, 256>>>(qkv_w,  wq, 3*DIM*DIM/4);
    wprep_kernel<<<(DIM*DIM/4   + 255)/256, 256>>>(proj_w, wp, DIM*DIM/4);
    wprep_kernel<<<(MLPH*DIM/4  + 255)/256, 256>>>(fc1_w,  w1, MLPH*DIM/4);
    wprep_kernel<<<(DIM*MLPH/4  + 255)/256, 256>>>(fc2_w,  w2, DIM*MLPH/4);

    // 1. LN1 + cyclic shift + window partition (tf32-rounded out)
    ln_kernel<1><<<ROWS, 128>>>(x, n1w, n1b, xw);
    // 2. QKV projection
    mma_gemm<0><<<dim3((3*DIM)/128, ROWS/128), 256, SMEM>>>(xw, wq, qkv_b, nullptr, qkvb, ROWS, 3*DIM, DIM);
    // 3. windowed attention (tf32-rounded out)
    attn_kernel<<<dim3(BATCH*NWIN, HEADS), 128>>>(qkvb, btab, att);
    // 4. proj + window reverse + unshift + shortcut residual
    mma_gemm<3><<<dim3(DIM/128, ROWS/128), 256, SMEM>>>(att, wp, proj_b, x, x1, ROWS, DIM, DIM);
    // 5. LN2 (tf32-rounded out)
    ln_kernel<0><<<ROWS, 128>>>(x1, n2w, n2b, z);
    // 6. fc1 + exact GELU (tf32-rounded out)
    mma_gemm<1><<<dim3(MLPH/128, ROWS/128), 256, SMEM>>>(z, w1, fc1_b, nullptr, hid, ROWS, MLPH, DIM);
    // 7. fc2 + residual -> final output
    mma_gemm<2><<<dim3(DIM/128, ROWS/128), 256, SMEM>>>(hid, w2, fc2_b, x1, out, ROWS, DIM, MLPH);
}

// round 6
// speedup vs baseline: 4.6505x; 1.0877x over previous
#include <cuda_runtime.h>
#include <math.h>
#include <stdint.h>

#define BATCH   64
#define HIMG    28
#define WIMG    28
#define DIM     384
#define HEADS   12
#define HD      32
#define WIN     7
#define SHIFT   3
#define NTOK    49
#define NWIN    16
#define ROWS    (BATCH*NWIN*NTOK)   // 50176
#define MLPH    1536

// ---------------- scratch ----------------------------------------------------
__device__ float g_xw [ROWS*DIM];
__device__ float g_qkv[ROWS*3*DIM];
__device__ float g_att[ROWS*DIM];
__device__ float g_x1 [ROWS*DIM];
__device__ float g_z  [ROWS*DIM];
__device__ float g_hid[(size_t)ROWS*MLPH];
// tf32-rounded weights
__device__ float g_wq[3*DIM*DIM];
__device__ float g_wp[DIM*DIM];
__device__ float g_w1[MLPH*DIM];
__device__ float g_w2[DIM*MLPH];
// combined bias+mask table: [4 window types][12 heads][49][49]
__device__ float g_tbl[48*NTOK*NTOK];

// ---------------- helpers ------------------------------------------------------
__device__ __forceinline__ uint32_t f2tf32(float x) {
    uint32_t r;
    asm("cvt.rna.tf32.f32 %0, %1;" : "=r"(r) : "f"(x));
    return r;
}
__device__ __forceinline__ float tf32r(float x) { return __uint_as_float(f2tf32(x)); }

__device__ __forceinline__ uint32_t smem_u32(const void* p) {
    uint32_t a;
    asm("{ .reg .u64 t; cvta.to.shared.u64 t, %1; cvt.u32.u64 %0, t; }" : "=r"(a) : "l"(p));
    return a;
}
__device__ __forceinline__ void cp16(uint32_t s, const void* g) {
    asm volatile("cp.async.cg.shared.global [%0], [%1], 16;" :: "r"(s), "l"(g));
}
#define CP_COMMIT() asm volatile("cp.async.commit_group;" ::: "memory")
#define CP_WAIT1()  asm volatile("cp.async.wait_group 1;" ::: "memory")

__device__ __forceinline__ void mma_tf32(float* d, const uint32_t* a, const uint32_t* b) {
    asm volatile(
        "mma.sync.aligned.m16n8k8.row.col.f32.tf32.tf32.f32 "
        "{%0,%1,%2,%3}, {%4,%5,%6,%7}, {%8,%9}, {%0,%1,%2,%3};"
        : "+f"(d[0]), "+f"(d[1]), "+f"(d[2]), "+f"(d[3])
        : "r"(a[0]), "r"(a[1]), "r"(a[2]), "r"(a[3]), "r"(b[0]), "r"(b[1]));
}

// ---------------- weight prep: tf32-round copy (all 4 matrices, 1 launch) ------
__global__ void wprep_all(const float* s0, float* d0, int n0,
                          const float* s1, float* d1, int n1,
                          const float* s2, float* d2, int n2,
                          const float* s3, float* d3, int n3) {
    int i = blockIdx.x * blockDim.x + threadIdx.x;
    const float* s; float* d; int j = i;
    if (j < n0) { s = s0; d = d0; }
    else { j -= n0; if (j < n1) { s = s1; d = d1; }
    else { j -= n1; if (j < n2) { s = s2; d = d2; }
    else { j -= n2; if (j >= n3) return; s = s3; d = d3; } } }
    float4 v = ((const float4*)s)[j];
    v.x = tf32r(v.x); v.y = tf32r(v.y); v.z = tf32r(v.z); v.w = tf32r(v.w);
    ((float4*)d)[j] = v;
}

// ---------------- bias+mask table build ----------------------------------------
__global__ void tbuild_kernel(const float* __restrict__ btab, float* __restrict__ tbl) {
    int th = blockIdx.x;
    int type = th / HEADS, h = th % HEADS;
    int eh = (type >> 1) & 1, ew = type & 1;
    for (int e = threadIdx.x; e < NTOK*NTOK; e += blockDim.x) {
        int n = e / NTOK, m = e % NTOK;
        int i1 = n/7, j1 = n%7, i2 = m/7, j2 = m%7;
        float v = btab[((i1 - i2 + 6)*13 + (j1 - j2 + 6))*HEADS + h];
        int r1 = (eh ? (i1 < 4 ? 1 : 2) : 0) * 3 + (ew ? (j1 < 4 ? 1 : 2) : 0);
        int r2 = (eh ? (i2 < 4 ? 1 : 2) : 0) * 3 + (ew ? (j2 < 4 ? 1 : 2) : 0);
        if (r1 != r2) v -= 100.f;
        tbl[th*NTOK*NTOK + e] = v;
    }
}

// ---------------- LayerNorm (optionally fused shift+window gather) -----------
template<int GATHER>
__global__ void ln_kernel(const float* __restrict__ x, const float* __restrict__ w,
                          const float* __restrict__ b, float* __restrict__ out) {
    int r = blockIdx.x;
    int src = r;
    if (GATHER) {
        int bb  = r / (NWIN*NTOK);
        int rem = r % (NWIN*NTOK);
        int win = rem / NTOK, n = rem % NTOK;
        int wh = win / 4, ww = win % 4;
        int i = n / 7, j = n % 7;
        int sh = (wh*7 + i + SHIFT) % HIMG;
        int sw = (ww*7 + j + SHIFT) % WIMG;
        src = bb*(HIMG*WIMG) + sh*WIMG + sw;
    }
    const float* xp = x + (size_t)src * DIM;
    int tid = threadIdx.x;
    float v0 = xp[tid], v1 = xp[tid+128], v2 = xp[tid+256];
    float s = v0 + v1 + v2;
    __shared__ float red[4];
    #pragma unroll
    for (int o = 16; o; o >>= 1) s += __shfl_xor_sync(~0u, s, o);
    if ((tid & 31) == 0) red[tid >> 5] = s;
    __syncthreads();
    float mean = (red[0]+red[1]+red[2]+red[3]) * (1.0f/DIM);
    float d0 = v0-mean, d1 = v1-mean, d2 = v2-mean;
    float q = d0*d0 + d1*d1 + d2*d2;
    #pragma unroll
    for (int o = 16; o; o >>= 1) q += __shfl_xor_sync(~0u, q, o);
    __syncthreads();
    if ((tid & 31) == 0) red[tid >> 5] = q;
    __syncthreads();
    float var = (red[0]+red[1]+red[2]+red[3]) * (1.0f/DIM);
    float inv = rsqrtf(var + 1e-5f);
    float* op = out + (size_t)r * DIM;
    op[tid]     = tf32r(d0*inv*w[tid]     + b[tid]);
    op[tid+128] = tf32r(d1*inv*w[tid+128] + b[tid+128]);
    op[tid+256] = tf32r(d2*inv*w[tid+256] + b[tid+256]);
}

// ---------------- pipelined tf32 GEMM (single sync per k-tile) -----------------
#define SSZ 8192   // u32 per stage (A 4096 + B 4096)
template<int MODE>
__global__ void __launch_bounds__(256, 2)
mma_gemm(const float* __restrict__ A, const float* __restrict__ W,
         const float* __restrict__ bias, const float* __restrict__ res,
         float* __restrict__ out, int M, int N, int K) {
    extern __shared__ __align__(16) uint32_t smem[];
    uint32_t sbase = smem_u32(smem);
    int tid  = threadIdx.x;
    int wid  = tid >> 5, lane = tid & 31;
    int wm   = wid >> 2, wn = wid & 3;
    int q    = lane >> 2, c = lane & 3;
    int m0   = blockIdx.y * 128, n0 = blockIdx.x * 128;

    int sr = tid >> 3;
    int sc = tid & 7;

    const float* Ag0 = A + (size_t)(m0 + sr) * K + sc*4;
    const float* Wg0 = W + (size_t)(n0 + sr) * K + sc*4;

    float acc[4][4][4];
    #pragma unroll
    for (int i = 0; i < 4; i++)
        #pragma unroll
        for (int j = 0; j < 4; j++)
            #pragma unroll
            for (int e = 0; e < 4; e++) acc[i][j][e] = 0.f;

    const int T = K >> 5;

    auto load_tile = [&](int t) {
        uint32_t sb = sbase + (uint32_t)(t % 3) * (SSZ*4);
        const float* Ag = Ag0 + t*32;
        const float* Wg = Wg0 + t*32;
        #pragma unroll
        for (int i = 0; i < 4; i++) {
            int m = sr + i*32;
            uint32_t off = (uint32_t)(m*128 + ((sc*16) ^ ((m & 7) * 16)));
            cp16(sb + off,         Ag + (size_t)i*32*K);
            cp16(sb + 16384 + off, Wg + (size_t)i*32*K);
        }
    };

    load_tile(0); CP_COMMIT();
    load_tile(1); CP_COMMIT();

    const int swz = q * 4;
    for (int t = 0; t < T; t++) {
        CP_WAIT1();
        __syncthreads();
        if (t + 2 < T) load_tile(t + 2);
        CP_COMMIT();

        const uint32_t* As = smem + (t % 3) * SSZ;
        const uint32_t* Bs = As + 4096;
        #pragma unroll
        for (int ks = 0; ks < 4; ks++) {
            int kb = ks * 8;
            int c0 = (kb + c) ^ swz;
            int c1 = (kb + c + 4) ^ swz;
            uint32_t af[4][4];
            #pragma unroll
            for (int mi = 0; mi < 4; mi++) {
                int r0 = wm*64 + mi*16 + q;
                af[mi][0] = As[r0*32 + c0];
                af[mi][1] = As[(r0+8)*32 + c0];
                af[mi][2] = As[r0*32 + c1];
                af[mi][3] = As[(r0+8)*32 + c1];
            }
            uint32_t bf[4][2];
            #pragma unroll
            for (int ni = 0; ni < 4; ni++) {
                int nr = wn*32 + ni*8 + q;
                bf[ni][0] = Bs[nr*32 + c0];
                bf[ni][1] = Bs[nr*32 + c1];
            }
            #pragma unroll
            for (int mi = 0; mi < 4; mi++)
                #pragma unroll
                for (int ni = 0; ni < 4; ni++)
                    mma_tf32(acc[mi][ni], af[mi], bf[ni]);
        }
    }

    // ---- epilogue ----
    #pragma unroll
    for (int mi = 0; mi < 4; mi++) {
        int r0 = m0 + wm*64 + mi*16 + q;
        int r1 = r0 + 8;
        size_t or0, or1;
        if (MODE == 3) {
            #pragma unroll
            for (int half = 0; half < 2; half++) {
                int m = half ? r1 : r0;
                int bbi = m / (NWIN*NTOK);
                int rem = m % (NWIN*NTOK);
                int win = rem / NTOK, n = rem % NTOK;
                int wh = win >> 2, ww = win & 3, ii = n / 7, jj = n % 7;
                int dh = (wh*7 + ii + SHIFT) % HIMG;
                int dw = (ww*7 + jj + SHIFT) % WIMG;
                size_t o = (size_t)bbi*(HIMG*WIMG) + dh*WIMG + dw;
                if (half) or1 = o; else or0 = o;
            }
        } else {
            or0 = (size_t)r0; or1 = (size_t)r1;
        }
        #pragma unroll
        for (int ni = 0; ni < 4; ni++) {
            int col = n0 + wn*32 + ni*8 + 2*c;
            float2 bv = *(const float2*)&bias[col];
            float v00 = acc[mi][ni][0] + bv.x, v01 = acc[mi][ni][1] + bv.y;
            float v10 = acc[mi][ni][2] + bv.x, v11 = acc[mi][ni][3] + bv.y;
            if (MODE == 1) {
                v00 = tf32r(0.5f*v00*(1.0f + erff(v00*0.70710678118654752f)));
                v01 = tf32r(0.5f*v01*(1.0f + erff(v01*0.70710678118654752f)));
                v10 = tf32r(0.5f*v10*(1.0f + erff(v10*0.70710678118654752f)));
                v11 = tf32r(0.5f*v11*(1.0f + erff(v11*0.70710678118654752f)));
            }
            if (MODE >= 2) {
                float2 ra = *(const float2*)&res[or0*N + col];
                float2 rb = *(const float2*)&res[or1*N + col];
                v00 += ra.x; v01 += ra.y; v10 += rb.x; v11 += rb.y;
            }
            float2 o0; o0.x = v00; o0.y = v01;
            float2 o1; o1.x = v10; o1.y = v11;
            *(float2*)&out[or0*N + col] = o0;
            *(float2*)&out[or1*N + col] = o1;
        }
    }
}

// ---------------- tensor-core windowed attention --------------------------------
// block = (window, head), 128 threads = 4 warps; warp w owns score rows [16w,16w+16)
// S[64x56] = Q[64x32] @ K^T, softmax (unnormalized P), O = P @ V, scale by 1/sum.
// SMEM plan (one flat array):
//   [0,2304)      qs   64 rows x 36     (dead after S-MMA)
//   [2304,4320)   kk   56 rows x 36     (dead after S-MMA)
//   [4320,6336)   vv   56 rows x 36
//   [6336,9536)   tsm  bias+mask (padded region: reads up to idx 3142 discarded)
//   ps = sm[0], 64 rows x 60  (aliases qs+kk; guarded by __syncthreads after S-MMA)
#define QSS 36
#define PSS 60
__global__ void __launch_bounds__(128)
attn_mma(const float* __restrict__ qkv, const float* __restrict__ tbl,
         float* __restrict__ out) {
    int bw = blockIdx.x, h = blockIdx.y;
    __shared__ float sm[9536];
    float* qs  = sm;
    float* kk  = sm + 2304;
    float* vv  = sm + 4320;
    float* tsm = sm + 6336;
    float* ps  = sm;            // aliases qs+kk after they are dead
    int tid = threadIdx.x;
    int wid = tid >> 5, lane = tid & 31;
    int q8 = lane >> 2, c4 = lane & 3;
    const float scale = 0.17677669529663689f;

    // stage q,k,v (tf32-rounded; q pre-scaled); zero padding rows
    for (int idx = tid; idx < 64*32; idx += 128) {
        int n = idx >> 5, d = idx & 31;
        float qv = 0.f, kv = 0.f, vvv = 0.f;
        if (n < NTOK) {
            size_t base = (size_t)(bw*NTOK + n)*(3*DIM) + h*HD + d;
            qv  = tf32r(qkv[base] * scale);
            kv  = tf32r(qkv[base + DIM]);
            vvv = tf32r(qkv[base + 2*DIM]);
        }
        qs[n*QSS + d] = qv;
        if (n < 56) { kk[n*QSS + d] = kv; vv[n*QSS + d] = vvv; }
    }
    // stage bias+mask table slab
    {
        int win = bw % NWIN;
        int type = ((win >> 2) == 3 ? 2 : 0) + ((win & 3) == 3 ? 1 : 0);
        const float* tp = tbl + (size_t)(type*HEADS + h)*NTOK*NTOK;
        for (int i = tid; i < NTOK*NTOK; i += 128) tsm[i] = tp[i];
    }
    __syncthreads();

    int row = wid*16 + q8;          // rows row, row+8

    // ---- S = Q @ K^T ----
    float s[7][4];
    #pragma unroll
    for (int nf = 0; nf < 7; nf++)
        #pragma unroll
        for (int e = 0; e < 4; e++) s[nf][e] = 0.f;
    #pragma unroll
    for (int ks = 0; ks < 4; ks++) {
        int kc = ks*8 + c4;
        uint32_t af[4];
        af[0] = __float_as_uint(qs[row*QSS + kc]);
        af[1] = __float_as_uint(qs[(row+8)*QSS + kc]);
        af[2] = __float_as_uint(qs[row*QSS + kc + 4]);
        af[3] = __float_as_uint(qs[(row+8)*QSS + kc + 4]);
        #pragma unroll
        for (int nf = 0; nf < 7; nf++) {
            uint32_t bf[2];
            bf[0] = __float_as_uint(kk[(nf*8 + q8)*QSS + kc]);
            bf[1] = __float_as_uint(kk[(nf*8 + q8)*QSS + kc + 4]);
            mma_tf32(s[nf], af, bf);
        }
    }
    __syncthreads();   // all warps done reading qs/kk before ps overwrites them

    // ---- add bias+mask, softmax over cols (unnormalized P into ps) ----
    bool rv0 = row < NTOK, rv1 = (row+8) < NTOK;
    float mx0 = -1e30f, mx1 = -1e30f;
    #pragma unroll
    for (int nf = 0; nf < 7; nf++) {
        int col0 = nf*8 + 2*c4, col1 = col0 + 1;
        bool cv0 = col0 < NTOK, cv1 = col1 < NTOK;
        s[nf][0] = (rv0 && cv0) ? s[nf][0] + tsm[row*NTOK + col0] : -1e30f;
        s[nf][1] = (rv0 && cv1) ? s[nf][1] + tsm[row*NTOK + col1] : -1e30f;
        s[nf][2] = (rv1 && cv0) ? s[nf][2] + tsm[(row+8)*NTOK + col0] : -1e30f;
        s[nf][3] = (rv1 && cv1) ? s[nf][3] + tsm[(row+8)*NTOK + col1] : -1e30f;
        mx0 = fmaxf(mx0, fmaxf(s[nf][0], s[nf][1]));
        mx1 = fmaxf(mx1, fmaxf(s[nf][2], s[nf][3]));
    }
    mx0 = fmaxf(mx0, __shfl_xor_sync(~0u, mx0, 1));
    mx0 = fmaxf(mx0, __shfl_xor_sync(~0u, mx0, 2));
    mx1 = fmaxf(mx1, __shfl_xor_sync(~0u, mx1, 1));
    mx1 = fmaxf(mx1, __shfl_xor_sync(~0u, mx1, 2));
    float sum0 = 0.f, sum1 = 0.f;
    #pragma unroll
    for (int nf = 0; nf < 7; nf++) {
        int col0 = nf*8 + 2*c4;
        float e0 = tf32r(__expf(s[nf][0] - mx0));
        float e1 = tf32r(__expf(s[nf][1] - mx0));
        float e2 = tf32r(__expf(s[nf][2] - mx1));
        float e3 = tf32r(__expf(s[nf][3] - mx1));
        sum0 += e0 + e1; sum1 += e2 + e3;
        float2 p0; p0.x = e0; p0.y = e1;
        float2 p1; p1.x = e2; p1.y = e3;
        *(float2*)&ps[row*PSS + col0]     = p0;
        *(float2*)&ps[(row+8)*PSS + col0] = p1;
    }
    sum0 += __shfl_xor_sync(~0u, sum0, 1);
    sum0 += __shfl_xor_sync(~0u, sum0, 2);
    sum1 += __shfl_xor_sync(~0u, sum1, 1);
    sum1 += __shfl_xor_sync(~0u, sum1, 2);
    float inv0 = 1.f / sum0, inv1 = 1.f / sum1;
    __syncwarp();      // each warp reads only the ps rows it wrote

    // ---- O = P @ V ----
    float o[4][4];
    #pragma unroll
    for (int ni = 0; ni < 4; ni++)
        #pragma unroll
        for (int e = 0; e < 4; e++) o[ni][e] = 0.f;
    #pragma unroll
    for (int kb = 0; kb < 56; kb += 8) {
        int kc = kb + c4;
        uint32_t af[4];
        af[0] = __float_as_uint(ps[row*PSS + kc]);
        af[1] = __float_as_uint(ps[(row+8)*PSS + kc]);
        af[2] = __float_as_uint(ps[row*PSS + kc + 4]);
        af[3] = __float_as_uint(ps[(row+8)*PSS + kc + 4]);
        #pragma unroll
        for (int ni = 0; ni < 4; ni++) {
            uint32_t bf[2];
            bf[0] = __float_as_uint(vv[kc*QSS + ni*8 + q8]);
            bf[1] = __float_as_uint(vv[(kc+4)*QSS + ni*8 + q8]);
            mma_tf32(o[ni], af, bf);
        }
    }

    // ---- store (tf32-rounded; feeds proj GEMM) ----
    #pragma unroll
    for (int ni = 0; ni < 4; ni++) {
        int d0 = ni*8 + 2*c4;
        if (rv0) {
            float2 ov; ov.x = tf32r(o[ni][0]*inv0); ov.y = tf32r(o[ni][1]*inv0);
            *(float2*)&out[(size_t)(bw*NTOK + row)*DIM + h*HD + d0] = ov;
        }
        if (rv1) {
            float2 ov; ov.x = tf32r(o[ni][2]*inv1); ov.y = tf32r(o[ni][3]*inv1);
            *(float2*)&out[(size_t)(bw*NTOK + row + 8)*DIM + h*HD + d0] = ov;
        }
    }
}

// ---------------- launcher -----------------------------------------------------
extern "C" void kernel_launch(void* const* d_in, const int* in_sizes, int n_in,
                              void* d_out, int out_size) {
    const float* x      = (const float*)d_in[0];
    const float* n1w    = (const float*)d_in[1];
    const float* n1b    = (const float*)d_in[2];
    const float* qkv_w  = (const float*)d_in[3];
    const float* qkv_b  = (const float*)d_in[4];
    const float* proj_w = (const float*)d_in[5];
    const float* proj_b = (const float*)d_in[6];
    const float* btab   = (const float*)d_in[7];
    const float* n2w    = (const float*)d_in[8];
    const float* n2b    = (const float*)d_in[9];
    const float* fc1_w  = (const float*)d_in[10];
    const float* fc1_b  = (const float*)d_in[11];
    const float* fc2_w  = (const float*)d_in[12];
    const float* fc2_b  = (const float*)d_in[13];
    float* out = (float*)d_out;

    float *xw, *qkvb, *att, *x1, *z, *hid, *wq, *wp, *w1, *w2, *tbl;
    cudaGetSymbolAddress((void**)&xw,   g_xw);
    cudaGetSymbolAddress((void**)&qkvb, g_qkv);
    cudaGetSymbolAddress((void**)&att,  g_att);
    cudaGetSymbolAddress((void**)&x1,   g_x1);
    cudaGetSymbolAddress((void**)&z,    g_z);
    cudaGetSymbolAddress((void**)&hid,  g_hid);
    cudaGetSymbolAddress((void**)&wq,   g_wq);
    cudaGetSymbolAddress((void**)&wp,   g_wp);
    cudaGetSymbolAddress((void**)&w1,   g_w1);
    cudaGetSymbolAddress((void**)&w2,   g_w2);
    cudaGetSymbolAddress((void**)&tbl,  g_tbl);

    const int SMEM = 3 * SSZ * 4;   // 98304 bytes
    static bool attr_done = false;
    if (!attr_done) {
        cudaFuncSetAttribute(mma_gemm<0>, cudaFuncAttributeMaxDynamicSharedMemorySize, SMEM);
        cudaFuncSetAttribute(mma_gemm<1>, cudaFuncAttributeMaxDynamicSharedMemorySize, SMEM);
        cudaFuncSetAttribute(mma_gemm<2>, cudaFuncAttributeMaxDynamicSharedMemorySize, SMEM);
        cudaFuncSetAttribute(mma_gemm<3>, cudaFuncAttributeMaxDynamicSharedMemorySize, SMEM);
        attr_done = true;
    }

    const int n0 = 3*DIM*DIM/4, n1 = DIM*DIM/4, n2 = MLPH*DIM/4, n3 = DIM*MLPH/4;
    // 0. tf32-round weights (1 launch) + bias/mask table
    wprep_all<<<(n0+n1+n2+n3 + 255)/256, 256>>>(qkv_w, wq, n0, proj_w, wp, n1,
                                                fc1_w, w1, n2, fc2_w, w2, n3);
    tbuild_kernel<<<48, 256>>>(btab, tbl);

    // 1. LN1 + cyclic shift + window partition (tf32-rounded out)
    ln_kernel<1><<<ROWS, 128>>>(x, n1w, n1b, xw);
    // 2. QKV projection
    mma_gemm<0><<<dim3((3*DIM)/128, ROWS/128), 256, SMEM>>>(xw, wq, qkv_b, nullptr, qkvb, ROWS, 3*DIM, DIM);
    // 3. windowed attention (tensor cores)
    attn_mma<<<dim3(BATCH*NWIN, HEADS), 128>>>(qkvb, tbl, att);
    // 4. proj + window reverse + unshift + shortcut residual
    mma_gemm<3><<<dim3(DIM/128, ROWS/128), 256, SMEM>>>(att, wp, proj_b, x, x1, ROWS, DIM, DIM);
    // 5. LN2 (tf32-rounded out)
    ln_kernel<0><<<ROWS, 128>>>(x1, n2w, n2b, z);
    // 6. fc1 + exact GELU (tf32-rounded out)
    mma_gemm<1><<<dim3(MLPH/128, ROWS/128), 256, SMEM>>>(z, w1, fc1_b, nullptr, hid, ROWS, MLPH, DIM);
    // 7. fc2 + residual -> final output
    mma_gemm<2><<<dim3(DIM/128, ROWS/128), 256, SMEM>>>(hid, w2, fc2_b, x1, out, ROWS, DIM, MLPH);
}

// round 7
// speedup vs baseline: 4.8606x; 1.0452x over previous
#include <cuda_runtime.h>
#include <math.h>
#include <stdint.h>

#define BATCH   64
#define HIMG    28
#define WIMG    28
#define DIM     384
#define HEADS   12
#define HD      32
#define WIN     7
#define SHIFT   3
#define NTOK    49
#define NWIN    16
#define ROWS    (BATCH*NWIN*NTOK)   // 50176
#define MLPH    1536

// ---------------- scratch ----------------------------------------------------
__device__ float g_xw [ROWS*DIM];
__device__ float g_qkv[ROWS*3*DIM];
__device__ float g_att[ROWS*DIM];
__device__ float g_x1 [ROWS*DIM];
__device__ float g_z  [ROWS*DIM];
__device__ float g_hid[(size_t)ROWS*MLPH];
// tf32-rounded weights
__device__ float g_wq[3*DIM*DIM];
__device__ float g_wp[DIM*DIM];
__device__ float g_w1[MLPH*DIM];
__device__ float g_w2[DIM*MLPH];
// combined bias+mask table: [4 window types][12 heads][49][49]
__device__ float g_tbl[48*NTOK*NTOK];

// ---------------- helpers ------------------------------------------------------
__device__ __forceinline__ uint32_t f2tf32(float x) {
    uint32_t r;
    asm("cvt.rna.tf32.f32 %0, %1;" : "=r"(r) : "f"(x));
    return r;
}
__device__ __forceinline__ float tf32r(float x) { return __uint_as_float(f2tf32(x)); }

__device__ __forceinline__ uint32_t smem_u32(const void* p) {
    uint32_t a;
    asm("{ .reg .u64 t; cvta.to.shared.u64 t, %1; cvt.u32.u64 %0, t; }" : "=r"(a) : "l"(p));
    return a;
}
__device__ __forceinline__ void cp16(uint32_t s, const void* g) {
    asm volatile("cp.async.cg.shared.global [%0], [%1], 16;" :: "r"(s), "l"(g));
}
#define CP_COMMIT() asm volatile("cp.async.commit_group;" ::: "memory")
#define CP_WAIT1()  asm volatile("cp.async.wait_group 1;" ::: "memory")

__device__ __forceinline__ void mma_tf32(float* d, const uint32_t* a, const uint32_t* b) {
    asm volatile(
        "mma.sync.aligned.m16n8k8.row.col.f32.tf32.tf32.f32 "
        "{%0,%1,%2,%3}, {%4,%5,%6,%7}, {%8,%9}, {%0,%1,%2,%3};"
        : "+f"(d[0]), "+f"(d[1]), "+f"(d[2]), "+f"(d[3])
        : "r"(a[0]), "r"(a[1]), "r"(a[2]), "r"(a[3]), "r"(b[0]), "r"(b[1]));
}

// ---------------- weight prep: tf32-round copy (all 4 matrices, 1 launch) ------
__global__ void wprep_all(const float* s0, float* d0, int n0,
                          const float* s1, float* d1, int n1,
                          const float* s2, float* d2, int n2,
                          const float* s3, float* d3, int n3) {
    int i = blockIdx.x * blockDim.x + threadIdx.x;
    const float* s; float* d; int j = i;
    if (j < n0) { s = s0; d = d0; }
    else { j -= n0; if (j < n1) { s = s1; d = d1; }
    else { j -= n1; if (j < n2) { s = s2; d = d2; }
    else { j -= n2; if (j >= n3) return; s = s3; d = d3; } } }
    float4 v = ((const float4*)s)[j];
    v.x = tf32r(v.x); v.y = tf32r(v.y); v.z = tf32r(v.z); v.w = tf32r(v.w);
    ((float4*)d)[j] = v;
}

// ---------------- bias+mask table build ----------------------------------------
__global__ void tbuild_kernel(const float* __restrict__ btab, float* __restrict__ tbl) {
    int th = blockIdx.x;
    int type = th / HEADS, h = th % HEADS;
    int eh = (type >> 1) & 1, ew = type & 1;
    for (int e = threadIdx.x; e < NTOK*NTOK; e += blockDim.x) {
        int n = e / NTOK, m = e % NTOK;
        int i1 = n/7, j1 = n%7, i2 = m/7, j2 = m%7;
        float v = btab[((i1 - i2 + 6)*13 + (j1 - j2 + 6))*HEADS + h];
        int r1 = (eh ? (i1 < 4 ? 1 : 2) : 0) * 3 + (ew ? (j1 < 4 ? 1 : 2) : 0);
        int r2 = (eh ? (i2 < 4 ? 1 : 2) : 0) * 3 + (ew ? (j2 < 4 ? 1 : 2) : 0);
        if (r1 != r2) v -= 100.f;
        tbl[th*NTOK*NTOK + e] = v;
    }
}

// ---------------- LayerNorm (optionally fused shift+window gather) -----------
template<int GATHER>
__global__ void ln_kernel(const float* __restrict__ x, const float* __restrict__ w,
                          const float* __restrict__ b, float* __restrict__ out) {
    int r = blockIdx.x;
    int src = r;
    if (GATHER) {
        int bb  = r / (NWIN*NTOK);
        int rem = r % (NWIN*NTOK);
        int win = rem / NTOK, n = rem % NTOK;
        int wh = win / 4, ww = win % 4;
        int i = n / 7, j = n % 7;
        int sh = (wh*7 + i + SHIFT) % HIMG;
        int sw = (ww*7 + j + SHIFT) % WIMG;
        src = bb*(HIMG*WIMG) + sh*WIMG + sw;
    }
    const float* xp = x + (size_t)src * DIM;
    int tid = threadIdx.x;
    float v0 = xp[tid], v1 = xp[tid+128], v2 = xp[tid+256];
    float s = v0 + v1 + v2;
    __shared__ float red[4];
    #pragma unroll
    for (int o = 16; o; o >>= 1) s += __shfl_xor_sync(~0u, s, o);
    if ((tid & 31) == 0) red[tid >> 5] = s;
    __syncthreads();
    float mean = (red[0]+red[1]+red[2]+red[3]) * (1.0f/DIM);
    float d0 = v0-mean, d1 = v1-mean, d2 = v2-mean;
    float q = d0*d0 + d1*d1 + d2*d2;
    #pragma unroll
    for (int o = 16; o; o >>= 1) q += __shfl_xor_sync(~0u, q, o);
    __syncthreads();
    if ((tid & 31) == 0) red[tid >> 5] = q;
    __syncthreads();
    float var = (red[0]+red[1]+red[2]+red[3]) * (1.0f/DIM);
    float inv = rsqrtf(var + 1e-5f);
    float* op = out + (size_t)r * DIM;
    op[tid]     = tf32r(d0*inv*w[tid]     + b[tid]);
    op[tid+128] = tf32r(d1*inv*w[tid+128] + b[tid+128]);
    op[tid+256] = tf32r(d2*inv*w[tid+256] + b[tid+256]);
}

// ---------------- pipelined tf32 GEMM, 4 warps, warp tile 64x64 ----------------
// CTA tile 128x128, 3-stage cp.async, single sync per k-tile.
// Warp grid 2x2 -> A and B each read by only 2 warps (crossbar traffic minimal).
#define SSZ 8192   // u32 per stage (A 4096 + B 4096)
template<int MODE>
__global__ void __launch_bounds__(128, 2)
mma_gemm(const float* __restrict__ A, const float* __restrict__ W,
         const float* __restrict__ bias, const float* __restrict__ res,
         float* __restrict__ out, int M, int N, int K) {
    extern __shared__ __align__(16) uint32_t smem[];
    uint32_t sbase = smem_u32(smem);
    int tid  = threadIdx.x;
    int wid  = tid >> 5, lane = tid & 31;
    int wm   = wid >> 1, wn = wid & 1;           // warp grid 2x2
    int q    = lane >> 2, c = lane & 3;
    int m0   = blockIdx.y * 128, n0 = blockIdx.x * 128;

    int sr = tid >> 3;          // 0..15 row base (x8 iters -> 128)
    int sc = tid & 7;           // 16B chunk along k

    const float* Ag0 = A + (size_t)(m0 + sr) * K + sc*4;
    const float* Wg0 = W + (size_t)(n0 + sr) * K + sc*4;

    float acc[4][8][4];
    #pragma unroll
    for (int i = 0; i < 4; i++)
        #pragma unroll
        for (int j = 0; j < 8; j++)
            #pragma unroll
            for (int e = 0; e < 4; e++) acc[i][j][e] = 0.f;

    const int T = K >> 5;

    auto load_tile = [&](int t) {
        uint32_t sb = sbase + (uint32_t)(t % 3) * (SSZ*4);
        const float* Ag = Ag0 + t*32;
        const float* Wg = Wg0 + t*32;
        #pragma unroll
        for (int i = 0; i < 8; i++) {
            int m = sr + i*16;
            uint32_t off = (uint32_t)(m*128 + ((sc*16) ^ ((m & 7) * 16)));
            cp16(sb + off,         Ag + (size_t)i*16*K);
            cp16(sb + 16384 + off, Wg + (size_t)i*16*K);
        }
    };

    load_tile(0); CP_COMMIT();
    load_tile(1); CP_COMMIT();

    const int swz = q * 4;
    for (int t = 0; t < T; t++) {
        CP_WAIT1();
        __syncthreads();
        if (t + 2 < T) load_tile(t + 2);
        CP_COMMIT();

        const uint32_t* As = smem + (t % 3) * SSZ;
        const uint32_t* Bs = As + 4096;
        #pragma unroll
        for (int ks = 0; ks < 4; ks++) {
            int kb = ks * 8;
            int c0 = (kb + c) ^ swz;
            int c1 = (kb + c + 4) ^ swz;
            uint32_t af[4][4];
            #pragma unroll
            for (int mi = 0; mi < 4; mi++) {
                int r0 = wm*64 + mi*16 + q;
                af[mi][0] = As[r0*32 + c0];
                af[mi][1] = As[(r0+8)*32 + c0];
                af[mi][2] = As[r0*32 + c1];
                af[mi][3] = As[(r0+8)*32 + c1];
            }
            uint32_t bf[8][2];
            #pragma unroll
            for (int ni = 0; ni < 8; ni++) {
                int nr = wn*64 + ni*8 + q;
                bf[ni][0] = Bs[nr*32 + c0];
                bf[ni][1] = Bs[nr*32 + c1];
            }
            #pragma unroll
            for (int mi = 0; mi < 4; mi++)
                #pragma unroll
                for (int ni = 0; ni < 8; ni++)
                    mma_tf32(acc[mi][ni], af[mi], bf[ni]);
        }
    }

    // ---- epilogue ----
    #pragma unroll
    for (int mi = 0; mi < 4; mi++) {
        int r0 = m0 + wm*64 + mi*16 + q;
        int r1 = r0 + 8;
        size_t or0, or1;
        if (MODE == 3) {
            #pragma unroll
            for (int half = 0; half < 2; half++) {
                int m = half ? r1 : r0;
                int bbi = m / (NWIN*NTOK);
                int rem = m % (NWIN*NTOK);
                int win = rem / NTOK, n = rem % NTOK;
                int wh = win >> 2, ww = win & 3, ii = n / 7, jj = n % 7;
                int dh = (wh*7 + ii + SHIFT) % HIMG;
                int dw = (ww*7 + jj + SHIFT) % WIMG;
                size_t o = (size_t)bbi*(HIMG*WIMG) + dh*WIMG + dw;
                if (half) or1 = o; else or0 = o;
            }
        } else {
            or0 = (size_t)r0; or1 = (size_t)r1;
        }
        #pragma unroll
        for (int ni = 0; ni < 8; ni++) {
            int col = n0 + wn*64 + ni*8 + 2*c;
            float2 bv = *(const float2*)&bias[col];
            float v00 = acc[mi][ni][0] + bv.x, v01 = acc[mi][ni][1] + bv.y;
            float v10 = acc[mi][ni][2] + bv.x, v11 = acc[mi][ni][3] + bv.y;
            if (MODE == 1) {
                v00 = tf32r(0.5f*v00*(1.0f + erff(v00*0.70710678118654752f)));
                v01 = tf32r(0.5f*v01*(1.0f + erff(v01*0.70710678118654752f)));
                v10 = tf32r(0.5f*v10*(1.0f + erff(v10*0.70710678118654752f)));
                v11 = tf32r(0.5f*v11*(1.0f + erff(v11*0.70710678118654752f)));
            }
            if (MODE >= 2) {
                float2 ra = *(const float2*)&res[or0*N + col];
                float2 rb = *(const float2*)&res[or1*N + col];
                v00 += ra.x; v01 += ra.y; v10 += rb.x; v11 += rb.y;
            }
            float2 o0; o0.x = v00; o0.y = v01;
            float2 o1; o1.x = v10; o1.y = v11;
            *(float2*)&out[or0*N + col] = o0;
            *(float2*)&out[or1*N + col] = o1;
        }
    }
}

// ---------------- tensor-core windowed attention --------------------------------
#define QSS 36
#define PSS 60
__global__ void __launch_bounds__(128)
attn_mma(const float* __restrict__ qkv, const float* __restrict__ tbl,
         float* __restrict__ out) {
    int bw = blockIdx.x, h = blockIdx.y;
    __shared__ float sm[9536];
    float* qs  = sm;
    float* kk  = sm + 2304;
    float* vv  = sm + 4320;
    float* tsm = sm + 6336;
    float* ps  = sm;            // aliases qs+kk after they are dead
    int tid = threadIdx.x;
    int wid = tid >> 5, lane = tid & 31;
    int q8 = lane >> 2, c4 = lane & 3;
    const float scale = 0.17677669529663689f;

    for (int idx = tid; idx < 64*32; idx += 128) {
        int n = idx >> 5, d = idx & 31;
        float qv = 0.f, kv = 0.f, vvv = 0.f;
        if (n < NTOK) {
            size_t base = (size_t)(bw*NTOK + n)*(3*DIM) + h*HD + d;
            qv  = tf32r(qkv[base] * scale);
            kv  = tf32r(qkv[base + DIM]);
            vvv = tf32r(qkv[base + 2*DIM]);
        }
        qs[n*QSS + d] = qv;
        if (n < 56) { kk[n*QSS + d] = kv; vv[n*QSS + d] = vvv; }
    }
    {
        int win = bw % NWIN;
        int type = ((win >> 2) == 3 ? 2 : 0) + ((win & 3) == 3 ? 1 : 0);
        const float* tp = tbl + (size_t)(type*HEADS + h)*NTOK*NTOK;
        for (int i = tid; i < NTOK*NTOK; i += 128) tsm[i] = tp[i];
    }
    __syncthreads();

    int row = wid*16 + q8;

    float s[7][4];
    #pragma unroll
    for (int nf = 0; nf < 7; nf++)
        #pragma unroll
        for (int e = 0; e < 4; e++) s[nf][e] = 0.f;
    #pragma unroll
    for (int ks = 0; ks < 4; ks++) {
        int kc = ks*8 + c4;
        uint32_t af[4];
        af[0] = __float_as_uint(qs[row*QSS + kc]);
        af[1] = __float_as_uint(qs[(row+8)*QSS + kc]);
        af[2] = __float_as_uint(qs[row*QSS + kc + 4]);
        af[3] = __float_as_uint(qs[(row+8)*QSS + kc + 4]);
        #pragma unroll
        for (int nf = 0; nf < 7; nf++) {
            uint32_t bf[2];
            bf[0] = __float_as_uint(kk[(nf*8 + q8)*QSS + kc]);
            bf[1] = __float_as_uint(kk[(nf*8 + q8)*QSS + kc + 4]);
            mma_tf32(s[nf], af, bf);
        }
    }
    __syncthreads();   // qs/kk dead; ps may overwrite

    bool rv0 = row < NTOK, rv1 = (row+8) < NTOK;
    float mx0 = -1e30f, mx1 = -1e30f;
    #pragma unroll
    for (int nf = 0; nf < 7; nf++) {
        int col0 = nf*8 + 2*c4, col1 = col0 + 1;
        bool cv0 = col0 < NTOK, cv1 = col1 < NTOK;
        s[nf][0] = (rv0 && cv0) ? s[nf][0] + tsm[row*NTOK + col0] : -1e30f;
        s[nf][1] = (rv0 && cv1) ? s[nf][1] + tsm[row*NTOK + col1] : -1e30f;
        s[nf][2] = (rv1 && cv0) ? s[nf][2] + tsm[(row+8)*NTOK + col0] : -1e30f;
        s[nf][3] = (rv1 && cv1) ? s[nf][3] + tsm[(row+8)*NTOK + col1] : -1e30f;
        mx0 = fmaxf(mx0, fmaxf(s[nf][0], s[nf][1]));
        mx1 = fmaxf(mx1, fmaxf(s[nf][2], s[nf][3]));
    }
    mx0 = fmaxf(mx0, __shfl_xor_sync(~0u, mx0, 1));
    mx0 = fmaxf(mx0, __shfl_xor_sync(~0u, mx0, 2));
    mx1 = fmaxf(mx1, __shfl_xor_sync(~0u, mx1, 1));
    mx1 = fmaxf(mx1, __shfl_xor_sync(~0u, mx1, 2));
    float sum0 = 0.f, sum1 = 0.f;
    #pragma unroll
    for (int nf = 0; nf < 7; nf++) {
        int col0 = nf*8 + 2*c4;
        float e0 = tf32r(__expf(s[nf][0] - mx0));
        float e1 = tf32r(__expf(s[nf][1] - mx0));
        float e2 = tf32r(__expf(s[nf][2] - mx1));
        float e3 = tf32r(__expf(s[nf][3] - mx1));
        sum0 += e0 + e1; sum1 += e2 + e3;
        float2 p0; p0.x = e0; p0.y = e1;
        float2 p1; p1.x = e2; p1.y = e3;
        *(float2*)&ps[row*PSS + col0]     = p0;
        *(float2*)&ps[(row+8)*PSS + col0] = p1;
    }
    sum0 += __shfl_xor_sync(~0u, sum0, 1);
    sum0 += __shfl_xor_sync(~0u, sum0, 2);
    sum1 += __shfl_xor_sync(~0u, sum1, 1);
    sum1 += __shfl_xor_sync(~0u, sum1, 2);
    float inv0 = 1.f / sum0, inv1 = 1.f / sum1;
    __syncwarp();

    float o[4][4];
    #pragma unroll
    for (int ni = 0; ni < 4; ni++)
        #pragma unroll
        for (int e = 0; e < 4; e++) o[ni][e] = 0.f;
    #pragma unroll
    for (int kb = 0; kb < 56; kb += 8) {
        int kc = kb + c4;
        uint32_t af[4];
        af[0] = __float_as_uint(ps[row*PSS + kc]);
        af[1] = __float_as_uint(ps[(row+8)*PSS + kc]);
        af[2] = __float_as_uint(ps[row*PSS + kc + 4]);
        af[3] = __float_as_uint(ps[(row+8)*PSS + kc + 4]);
        #pragma unroll
        for (int ni = 0; ni < 4; ni++) {
            uint32_t bf[2];
            bf[0] = __float_as_uint(vv[kc*QSS + ni*8 + q8]);
            bf[1] = __float_as_uint(vv[(kc+4)*QSS + ni*8 + q8]);
            mma_tf32(o[ni], af, bf);
        }
    }

    #pragma unroll
    for (int ni = 0; ni < 4; ni++) {
        int d0 = ni*8 + 2*c4;
        if (rv0) {
            float2 ov; ov.x = tf32r(o[ni][0]*inv0); ov.y = tf32r(o[ni][1]*inv0);
            *(float2*)&out[(size_t)(bw*NTOK + row)*DIM + h*HD + d0] = ov;
        }
        if (rv1) {
            float2 ov; ov.x = tf32r(o[ni][2]*inv1); ov.y = tf32r(o[ni][3]*inv1);
            *(float2*)&out[(size_t)(bw*NTOK + row + 8)*DIM + h*HD + d0] = ov;
        }
    }
}

// ---------------- launcher -----------------------------------------------------
extern "C" void kernel_launch(void* const* d_in, const int* in_sizes, int n_in,
                              void* d_out, int out_size) {
    const float* x      = (const float*)d_in[0];
    const float* n1w    = (const float*)d_in[1];
    const float* n1b    = (const float*)d_in[2];
    const float* qkv_w  = (const float*)d_in[3];
    const float* qkv_b  = (const float*)d_in[4];
    const float* proj_w = (const float*)d_in[5];
    const float* proj_b = (const float*)d_in[6];
    const float* btab   = (const float*)d_in[7];
    const float* n2w    = (const float*)d_in[8];
    const float* n2b    = (const float*)d_in[9];
    const float* fc1_w  = (const float*)d_in[10];
    const float* fc1_b  = (const float*)d_in[11];
    const float* fc2_w  = (const float*)d_in[12];
    const float* fc2_b  = (const float*)d_in[13];
    float* out = (float*)d_out;

    float *xw, *qkvb, *att, *x1, *z, *hid, *wq, *wp, *w1, *w2, *tbl;
    cudaGetSymbolAddress((void**)&xw,   g_xw);
    cudaGetSymbolAddress((void**)&qkvb, g_qkv);
    cudaGetSymbolAddress((void**)&att,  g_att);
    cudaGetSymbolAddress((void**)&x1,   g_x1);
    cudaGetSymbolAddress((void**)&z,    g_z);
    cudaGetSymbolAddress((void**)&hid,  g_hid);
    cudaGetSymbolAddress((void**)&wq,   g_wq);
    cudaGetSymbolAddress((void**)&wp,   g_wp);
    cudaGetSymbolAddress((void**)&w1,   g_w1);
    cudaGetSymbolAddress((void**)&w2,   g_w2);
    cudaGetSymbolAddress((void**)&tbl,  g_tbl);

    const int SMEM = 3 * SSZ * 4;   // 98304 bytes
    static bool attr_done = false;
    if (!attr_done) {
        cudaFuncSetAttribute(mma_gemm<0>, cudaFuncAttributeMaxDynamicSharedMemorySize, SMEM);
        cudaFuncSetAttribute(mma_gemm<1>, cudaFuncAttributeMaxDynamicSharedMemorySize, SMEM);
        cudaFuncSetAttribute(mma_gemm<2>, cudaFuncAttributeMaxDynamicSharedMemorySize, SMEM);
        cudaFuncSetAttribute(mma_gemm<3>, cudaFuncAttributeMaxDynamicSharedMemorySize, SMEM);
        attr_done = true;
    }

    const int n0 = 3*DIM*DIM/4, n1 = DIM*DIM/4, n2 = MLPH*DIM/4, n3 = DIM*MLPH/4;
    wprep_all<<<(n0+n1+n2+n3 + 255)/256, 256>>>(qkv_w, wq, n0, proj_w, wp, n1,
                                                fc1_w, w1, n2, fc2_w, w2, n3);
    tbuild_kernel<<<48, 256>>>(btab, tbl);

    // 1. LN1 + cyclic shift + window partition (tf32-rounded out)
    ln_kernel<1><<<ROWS, 128>>>(x, n1w, n1b, xw);
    // 2. QKV projection
    mma_gemm<0><<<dim3((3*DIM)/128, ROWS/128), 128, SMEM>>>(xw, wq, qkv_b, nullptr, qkvb, ROWS, 3*DIM, DIM);
    // 3. windowed attention (tensor cores)
    attn_mma<<<dim3(BATCH*NWIN, HEADS), 128>>>(qkvb, tbl, att);
    // 4. proj + window reverse + unshift + shortcut residual
    mma_gemm<3><<<dim3(DIM/128, ROWS/128), 128, SMEM>>>(att, wp, proj_b, x, x1, ROWS, DIM, DIM);
    // 5. LN2 (tf32-rounded out)
    ln_kernel<0><<<ROWS, 128>>>(x1, n2w, n2b, z);
    // 6. fc1 + exact GELU (tf32-rounded out)
    mma_gemm<1><<<dim3(MLPH/128, ROWS/128), 128, SMEM>>>(z, w1, fc1_b, nullptr, hid, ROWS, MLPH, DIM);
    // 7. fc2 + residual -> final output
    mma_gemm<2><<<dim3(DIM/128, ROWS/128), 128, SMEM>>>(hid, w2, fc2_b, x1, out, ROWS, DIM, MLPH);
}

// round 8
// speedup vs baseline: 7.8163x; 1.6081x over previous
#include <cuda_runtime.h>
#include <cuda_fp16.h>
#include <math.h>
#include <stdint.h>

#define BATCH   64
#define HIMG    28
#define WIMG    28
#define DIM     384
#define HEADS   12
#define HD      32
#define WIN     7
#define SHIFT   3
#define NTOK    49
#define NWIN    16
#define ROWS    (BATCH*NWIN*NTOK)   // 50176
#define MLPH    1536

// ---------------- scratch ----------------------------------------------------
__device__ __half g_xw [ROWS*DIM];
__device__ __half g_qkv[ROWS*3*DIM];
__device__ __half g_att[ROWS*DIM];
__device__ float  g_x1 [ROWS*DIM];
__device__ __half g_z  [ROWS*DIM];
__device__ __half g_hid[(size_t)ROWS*MLPH];
// fp16 weights
__device__ __half g_wq[3*DIM*DIM];
__device__ __half g_wp[DIM*DIM];
__device__ __half g_w1[MLPH*DIM];
__device__ __half g_w2[DIM*MLPH];
// combined bias+mask table: [4 window types][12 heads][49][49]
__device__ float g_tbl[48*NTOK*NTOK];

// ---------------- helpers ------------------------------------------------------
__device__ __forceinline__ uint32_t smem_u32(const void* p) {
    uint32_t a;
    asm("{ .reg .u64 t; cvta.to.shared.u64 t, %1; cvt.u32.u64 %0, t; }" : "=r"(a) : "l"(p));
    return a;
}
__device__ __forceinline__ void cp16(uint32_t s, const void* g) {
    asm volatile("cp.async.cg.shared.global [%0], [%1], 16;" :: "r"(s), "l"(g));
}
#define CP_COMMIT() asm volatile("cp.async.commit_group;" ::: "memory")
#define CP_WAIT1()  asm volatile("cp.async.wait_group 1;" ::: "memory")

__device__ __forceinline__ void mma_f16(float* d, const uint32_t* a, const uint32_t* b) {
    asm volatile(
        "mma.sync.aligned.m16n8k16.row.col.f32.f16.f16.f32 "
        "{%0,%1,%2,%3}, {%4,%5,%6,%7}, {%8,%9}, {%0,%1,%2,%3};"
        : "+f"(d[0]), "+f"(d[1]), "+f"(d[2]), "+f"(d[3])
        : "r"(a[0]), "r"(a[1]), "r"(a[2]), "r"(a[3]), "r"(b[0]), "r"(b[1]));
}

// ---------------- weight prep: fp32 -> fp16 (all 4 matrices, 1 launch) ---------
__global__ void wprep_all(const float* s0, __half* d0, int n0,
                          const float* s1, __half* d1, int n1,
                          const float* s2, __half* d2, int n2,
                          const float* s3, __half* d3, int n3) {
    int i = blockIdx.x * blockDim.x + threadIdx.x;
    const float* s; __half* d; int j = i;
    if (j < n0) { s = s0; d = d0; }
    else { j -= n0; if (j < n1) { s = s1; d = d1; }
    else { j -= n1; if (j < n2) { s = s2; d = d2; }
    else { j -= n2; if (j >= n3) return; s = s3; d = d3; } } }
    float4 v = ((const float4*)s)[j];
    __half2* dp = (__half2*)(d + j*4);
    dp[0] = __floats2half2_rn(v.x, v.y);
    dp[1] = __floats2half2_rn(v.z, v.w);
}

// ---------------- bias+mask table build ----------------------------------------
__global__ void tbuild_kernel(const float* __restrict__ btab, float* __restrict__ tbl) {
    int th = blockIdx.x;
    int type = th / HEADS, h = th % HEADS;
    int eh = (type >> 1) & 1, ew = type & 1;
    for (int e = threadIdx.x; e < NTOK*NTOK; e += blockDim.x) {
        int n = e / NTOK, m = e % NTOK;
        int i1 = n/7, j1 = n%7, i2 = m/7, j2 = m%7;
        float v = btab[((i1 - i2 + 6)*13 + (j1 - j2 + 6))*HEADS + h];
        int r1 = (eh ? (i1 < 4 ? 1 : 2) : 0) * 3 + (ew ? (j1 < 4 ? 1 : 2) : 0);
        int r2 = (eh ? (i2 < 4 ? 1 : 2) : 0) * 3 + (ew ? (j2 < 4 ? 1 : 2) : 0);
        if (r1 != r2) v -= 100.f;
        tbl[th*NTOK*NTOK + e] = v;
    }
}

// ---------------- LayerNorm (optionally fused shift+window gather), half out ---
template<int GATHER>
__global__ void ln_kernel(const float* __restrict__ x, const float* __restrict__ w,
                          const float* __restrict__ b, __half* __restrict__ out) {
    int r = blockIdx.x;
    int src = r;
    if (GATHER) {
        int bb  = r / (NWIN*NTOK);
        int rem = r % (NWIN*NTOK);
        int win = rem / NTOK, n = rem % NTOK;
        int wh = win / 4, ww = win % 4;
        int i = n / 7, j = n % 7;
        int sh = (wh*7 + i + SHIFT) % HIMG;
        int sw = (ww*7 + j + SHIFT) % WIMG;
        src = bb*(HIMG*WIMG) + sh*WIMG + sw;
    }
    const float* xp = x + (size_t)src * DIM;
    int tid = threadIdx.x;
    float v0 = xp[tid], v1 = xp[tid+128], v2 = xp[tid+256];
    float s = v0 + v1 + v2;
    __shared__ float red[4];
    #pragma unroll
    for (int o = 16; o; o >>= 1) s += __shfl_xor_sync(~0u, s, o);
    if ((tid & 31) == 0) red[tid >> 5] = s;
    __syncthreads();
    float mean = (red[0]+red[1]+red[2]+red[3]) * (1.0f/DIM);
    float d0 = v0-mean, d1 = v1-mean, d2 = v2-mean;
    float q = d0*d0 + d1*d1 + d2*d2;
    #pragma unroll
    for (int o = 16; o; o >>= 1) q += __shfl_xor_sync(~0u, q, o);
    __syncthreads();
    if ((tid & 31) == 0) red[tid >> 5] = q;
    __syncthreads();
    float var = (red[0]+red[1]+red[2]+red[3]) * (1.0f/DIM);
    float inv = rsqrtf(var + 1e-5f);
    __half* op = out + (size_t)r * DIM;
    op[tid]     = __float2half_rn(d0*inv*w[tid]     + b[tid]);
    op[tid+128] = __float2half_rn(d1*inv*w[tid+128] + b[tid+128]);
    op[tid+256] = __float2half_rn(d2*inv*w[tid+256] + b[tid+256]);
}

// ---------------- pipelined fp16 GEMM, 4 warps, warp tile 64x64 ----------------
// CTA tile 128x128, BK=64 halves (128B/row), 3-stage cp.async, 1 sync per tile.
// MODE 0: +bias -> half | 1: gelu(+bias) -> half | 2: +bias+res -> f32
// MODE 3: +bias+res scatter -> f32
#define SSZ 8192   // u32 per stage (A 4096 + B 4096)
template<int MODE>
__global__ void __launch_bounds__(128, 2)
mma_gemm(const __half* __restrict__ A, const __half* __restrict__ W,
         const float* __restrict__ bias, const float* __restrict__ res,
         void* __restrict__ outv, int M, int N, int K) {
    extern __shared__ __align__(16) uint32_t smem[];
    uint32_t sbase = smem_u32(smem);
    int tid  = threadIdx.x;
    int wid  = tid >> 5, lane = tid & 31;
    int wm   = wid >> 1, wn = wid & 1;           // warp grid 2x2
    int q    = lane >> 2, c = lane & 3;
    int m0   = blockIdx.y * 128, n0 = blockIdx.x * 128;

    int sr = tid >> 3;          // 0..15 row base (x8 -> 128 rows)
    int sc = tid & 7;           // 16B chunk along k (8 per 128B row)

    const __half* Ag0 = A + (size_t)(m0 + sr) * K + sc*8;
    const __half* Wg0 = W + (size_t)(n0 + sr) * K + sc*8;

    float acc[4][8][4];
    #pragma unroll
    for (int i = 0; i < 4; i++)
        #pragma unroll
        for (int j = 0; j < 8; j++)
            #pragma unroll
            for (int e = 0; e < 4; e++) acc[i][j][e] = 0.f;

    const int T = K >> 6;       // BK = 64 halves

    auto load_tile = [&](int t) {
        uint32_t sb = sbase + (uint32_t)(t % 3) * (SSZ*4);
        const __half* Ag = Ag0 + t*64;
        const __half* Wg = Wg0 + t*64;
        #pragma unroll
        for (int i = 0; i < 8; i++) {
            int m = sr + i*16;
            uint32_t off = (uint32_t)(m*128 + ((sc*16) ^ ((m & 7) * 16)));
            cp16(sb + off,         Ag + (size_t)i*16*K);
            cp16(sb + 16384 + off, Wg + (size_t)i*16*K);
        }
    };

    load_tile(0); CP_COMMIT();
    load_tile(1); CP_COMMIT();

    const int swz = q * 4;
    for (int t = 0; t < T; t++) {
        CP_WAIT1();
        __syncthreads();
        if (t + 2 < T) load_tile(t + 2);
        CP_COMMIT();

        const uint32_t* As = smem + (t % 3) * SSZ;
        const uint32_t* Bs = As + 4096;
        #pragma unroll
        for (int ks = 0; ks < 4; ks++) {       // 4 x k16
            int kb = ks * 8;
            int c0 = (kb + c) ^ swz;
            int c1 = (kb + c + 4) ^ swz;
            uint32_t af[4][4];
            #pragma unroll
            for (int mi = 0; mi < 4; mi++) {
                int r0 = wm*64 + mi*16 + q;
                af[mi][0] = As[r0*32 + c0];
                af[mi][1] = As[(r0+8)*32 + c0];
                af[mi][2] = As[r0*32 + c1];
                af[mi][3] = As[(r0+8)*32 + c1];
            }
            uint32_t bf[8][2];
            #pragma unroll
            for (int ni = 0; ni < 8; ni++) {
                int nr = wn*64 + ni*8 + q;
                bf[ni][0] = Bs[nr*32 + c0];
                bf[ni][1] = Bs[nr*32 + c1];
            }
            #pragma unroll
            for (int mi = 0; mi < 4; mi++)
                #pragma unroll
                for (int ni = 0; ni < 8; ni++)
                    mma_f16(acc[mi][ni], af[mi], bf[ni]);
        }
    }

    // ---- epilogue ----
    #pragma unroll
    for (int mi = 0; mi < 4; mi++) {
        int r0 = m0 + wm*64 + mi*16 + q;
        int r1 = r0 + 8;
        size_t or0, or1;
        if (MODE == 3) {
            #pragma unroll
            for (int half_ = 0; half_ < 2; half_++) {
                int m = half_ ? r1 : r0;
                int bbi = m / (NWIN*NTOK);
                int rem = m % (NWIN*NTOK);
                int win = rem / NTOK, n = rem % NTOK;
                int wh = win >> 2, ww = win & 3, ii = n / 7, jj = n % 7;
                int dh = (wh*7 + ii + SHIFT) % HIMG;
                int dw = (ww*7 + jj + SHIFT) % WIMG;
                size_t o = (size_t)bbi*(HIMG*WIMG) + dh*WIMG + dw;
                if (half_) or1 = o; else or0 = o;
            }
        } else {
            or0 = (size_t)r0; or1 = (size_t)r1;
        }
        #pragma unroll
        for (int ni = 0; ni < 8; ni++) {
            int col = n0 + wn*64 + ni*8 + 2*c;
            float2 bv = *(const float2*)&bias[col];
            float v00 = acc[mi][ni][0] + bv.x, v01 = acc[mi][ni][1] + bv.y;
            float v10 = acc[mi][ni][2] + bv.x, v11 = acc[mi][ni][3] + bv.y;
            if (MODE == 1) {
                v00 = 0.5f*v00*(1.0f + erff(v00*0.70710678118654752f));
                v01 = 0.5f*v01*(1.0f + erff(v01*0.70710678118654752f));
                v10 = 0.5f*v10*(1.0f + erff(v10*0.70710678118654752f));
                v11 = 0.5f*v11*(1.0f + erff(v11*0.70710678118654752f));
            }
            if (MODE >= 2) {
                float2 ra = *(const float2*)&res[or0*N + col];
                float2 rb = *(const float2*)&res[or1*N + col];
                v00 += ra.x; v01 += ra.y; v10 += rb.x; v11 += rb.y;
            }
            if (MODE == 0 || MODE == 1) {
                __half* O = (__half*)outv;
                *(__half2*)&O[or0*N + col] = __floats2half2_rn(v00, v01);
                *(__half2*)&O[or1*N + col] = __floats2half2_rn(v10, v11);
            } else {
                float* O = (float*)outv;
                float2 o0; o0.x = v00; o0.y = v01;
                float2 o1; o1.x = v10; o1.y = v11;
                *(float2*)&O[or0*N + col] = o0;
                *(float2*)&O[or1*N + col] = o1;
            }
        }
    }
}

// ---------------- fp16 tensor-core windowed attention --------------------------
// block = (window, head), 4 warps; warp w owns score rows [16w, 16w+16).
// smem (u32): qs 64x20 | kk 56x20 | vvT 32x36 (V k-packed) | tsm(float) 3200
// ps (P, half2) 64x36 aliases qs+kk after S-phase.
#define QS2 20
#define VS2 36
#define PS2 36
__global__ void __launch_bounds__(128)
attn_mma(const __half* __restrict__ qkv, const float* __restrict__ tbl,
         __half* __restrict__ out) {
    int bw = blockIdx.x, h = blockIdx.y;
    __shared__ uint32_t sm[6752];
    uint32_t* qs  = sm;                 // 1280
    uint32_t* kkp = sm + 1280;          // 1120
    uint32_t* vvT = sm + 2400;          // 1152
    float*    tsm = (float*)(sm + 3552);// 3200 floats
    uint32_t* ps  = sm;                 // 2304 (aliases qs+kk)
    __half* qsh = (__half*)qs;
    __half* kkh = (__half*)kkp;
    __half* vvh = (__half*)vvT;
    int tid = threadIdx.x;
    int wid = tid >> 5, lane = tid & 31;
    int q8 = lane >> 2, c4 = lane & 3;
    const float scale = 0.17677669529663689f;

    // stage q (scaled), k, and V k-packed (vvT[d][token]); zeros in padding
    for (int idx = tid; idx < 64*32; idx += 128) {
        int n = idx >> 5, d = idx & 31;
        float qv = 0.f, kv = 0.f, vv_ = 0.f;
        if (n < NTOK) {
            size_t base = (size_t)(bw*NTOK + n)*(3*DIM) + h*HD + d;
            qv  = __half2float(qkv[base]) * scale;
            kv  = __half2float(qkv[base + DIM]);
            vv_ = __half2float(qkv[base + 2*DIM]);
        }
        qsh[n*(QS2*2) + d] = __float2half_rn(qv);
        if (n < 56) kkh[n*(QS2*2) + d] = __float2half_rn(kv);
        vvh[d*(VS2*2) + n] = __float2half_rn(vv_);
    }
    {
        int win = bw % NWIN;
        int type = ((win >> 2) == 3 ? 2 : 0) + ((win & 3) == 3 ? 1 : 0);
        const float* tp = tbl + (size_t)(type*HEADS + h)*NTOK*NTOK;
        for (int i = tid; i < NTOK*NTOK; i += 128) tsm[i] = tp[i];
    }
    __syncthreads();

    int row = wid*16 + q8;

    // ---- S = Q @ K^T (2 x k16) ----
    float s[7][4];
    #pragma unroll
    for (int nf = 0; nf < 7; nf++)
        #pragma unroll
        for (int e = 0; e < 4; e++) s[nf][e] = 0.f;
    #pragma unroll
    for (int ks = 0; ks < 2; ks++) {
        int kb = ks*8;
        uint32_t af[4];
        af[0] = qs[row*QS2 + kb + c4];
        af[1] = qs[(row+8)*QS2 + kb + c4];
        af[2] = qs[row*QS2 + kb + c4 + 4];
        af[3] = qs[(row+8)*QS2 + kb + c4 + 4];
        #pragma unroll
        for (int nf = 0; nf < 7; nf++) {
            uint32_t bf[2];
            bf[0] = kkp[(nf*8 + q8)*QS2 + kb + c4];
            bf[1] = kkp[(nf*8 + q8)*QS2 + kb + c4 + 4];
            mma_f16(s[nf], af, bf);
        }
    }
    __syncthreads();   // qs/kk dead; ps may overwrite

    // ---- bias+mask, softmax (unnormalized P into ps as half2) ----
    bool rv0 = row < NTOK, rv1 = (row+8) < NTOK;
    float mx0 = -1e30f, mx1 = -1e30f;
    #pragma unroll
    for (int nf = 0; nf < 7; nf++) {
        int col0 = nf*8 + 2*c4, col1 = col0 + 1;
        bool cv0 = col0 < NTOK, cv1 = col1 < NTOK;
        s[nf][0] = (rv0 && cv0) ? s[nf][0] + tsm[row*NTOK + col0] : -1e30f;
        s[nf][1] = (rv0 && cv1) ? s[nf][1] + tsm[row*NTOK + col1] : -1e30f;
        s[nf][2] = (rv1 && cv0) ? s[nf][2] + tsm[(row+8)*NTOK + col0] : -1e30f;
        s[nf][3] = (rv1 && cv1) ? s[nf][3] + tsm[(row+8)*NTOK + col1] : -1e30f;
        mx0 = fmaxf(mx0, fmaxf(s[nf][0], s[nf][1]));
        mx1 = fmaxf(mx1, fmaxf(s[nf][2], s[nf][3]));
    }
    mx0 = fmaxf(mx0, __shfl_xor_sync(~0u, mx0, 1));
    mx0 = fmaxf(mx0, __shfl_xor_sync(~0u, mx0, 2));
    mx1 = fmaxf(mx1, __shfl_xor_sync(~0u, mx1, 1));
    mx1 = fmaxf(mx1, __shfl_xor_sync(~0u, mx1, 2));
    float sum0 = 0.f, sum1 = 0.f;
    #pragma unroll
    for (int nf = 0; nf < 7; nf++) {
        float e0 = __expf(s[nf][0] - mx0);
        float e1 = __expf(s[nf][1] - mx0);
        float e2 = __expf(s[nf][2] - mx1);
        float e3 = __expf(s[nf][3] - mx1);
        sum0 += e0 + e1; sum1 += e2 + e3;
        __half2 p0 = __floats2half2_rn(e0, e1);
        __half2 p1 = __floats2half2_rn(e2, e3);
        ps[row*PS2 + nf*4 + c4]     = *(uint32_t*)&p0;
        ps[(row+8)*PS2 + nf*4 + c4] = *(uint32_t*)&p1;
    }
    // zero padded token columns 56..63 (u32 cols 28..31)
    ps[row*PS2 + 28 + c4]     = 0;
    ps[(row+8)*PS2 + 28 + c4] = 0;
    sum0 += __shfl_xor_sync(~0u, sum0, 1);
    sum0 += __shfl_xor_sync(~0u, sum0, 2);
    sum1 += __shfl_xor_sync(~0u, sum1, 1);
    sum1 += __shfl_xor_sync(~0u, sum1, 2);
    float inv0 = 1.f / sum0, inv1 = 1.f / sum1;
    __syncwarp();      // each warp reads only the ps rows it wrote

    // ---- O = P @ V (4 x k16 over 64 padded tokens) ----
    float o[4][4];
    #pragma unroll
    for (int ni = 0; ni < 4; ni++)
        #pragma unroll
        for (int e = 0; e < 4; e++) o[ni][e] = 0.f;
    #pragma unroll
    for (int ks = 0; ks < 4; ks++) {
        int kb = ks*8;
        uint32_t af[4];
        af[0] = ps[row*PS2 + kb + c4];
        af[1] = ps[(row+8)*PS2 + kb + c4];
        af[2] = ps[row*PS2 + kb + c4 + 4];
        af[3] = ps[(row+8)*PS2 + kb + c4 + 4];
        #pragma unroll
        for (int ni = 0; ni < 4; ni++) {
            uint32_t bf[2];
            bf[0] = vvT[(ni*8 + q8)*VS2 + kb + c4];
            bf[1] = vvT[(ni*8 + q8)*VS2 + kb + c4 + 4];
            mma_f16(o[ni], af, bf);
        }
    }

    // ---- store half2 ----
    #pragma unroll
    for (int ni = 0; ni < 4; ni++) {
        int d0 = ni*8 + 2*c4;
        if (rv0) {
            __half2 hv = __floats2half2_rn(o[ni][0]*inv0, o[ni][1]*inv0);
            *(__half2*)&out[(size_t)(bw*NTOK + row)*DIM + h*HD + d0] = hv;
        }
        if (rv1) {
            __half2 hv = __floats2half2_rn(o[ni][2]*inv1, o[ni][3]*inv1);
            *(__half2*)&out[(size_t)(bw*NTOK + row + 8)*DIM + h*HD + d0] = hv;
        }
    }
}

// ---------------- launcher -----------------------------------------------------
extern "C" void kernel_launch(void* const* d_in, const int* in_sizes, int n_in,
                              void* d_out, int out_size) {
    const float* x      = (const float*)d_in[0];
    const float* n1w    = (const float*)d_in[1];
    const float* n1b    = (const float*)d_in[2];
    const float* qkv_w  = (const float*)d_in[3];
    const float* qkv_b  = (const float*)d_in[4];
    const float* proj_w = (const float*)d_in[5];
    const float* proj_b = (const float*)d_in[6];
    const float* btab   = (const float*)d_in[7];
    const float* n2w    = (const float*)d_in[8];
    const float* n2b    = (const float*)d_in[9];
    const float* fc1_w  = (const float*)d_in[10];
    const float* fc1_b  = (const float*)d_in[11];
    const float* fc2_w  = (const float*)d_in[12];
    const float* fc2_b  = (const float*)d_in[13];
    float* out = (float*)d_out;

    __half *xw, *qkvb, *att, *z, *hid, *wq, *wp, *w1, *w2;
    float *x1, *tbl;
    cudaGetSymbolAddress((void**)&xw,   g_xw);
    cudaGetSymbolAddress((void**)&qkvb, g_qkv);
    cudaGetSymbolAddress((void**)&att,  g_att);
    cudaGetSymbolAddress((void**)&x1,   g_x1);
    cudaGetSymbolAddress((void**)&z,    g_z);
    cudaGetSymbolAddress((void**)&hid,  g_hid);
    cudaGetSymbolAddress((void**)&wq,   g_wq);
    cudaGetSymbolAddress((void**)&wp,   g_wp);
    cudaGetSymbolAddress((void**)&w1,   g_w1);
    cudaGetSymbolAddress((void**)&w2,   g_w2);
    cudaGetSymbolAddress((void**)&tbl,  g_tbl);

    const int SMEM = 3 * SSZ * 4;   // 98304 bytes
    static bool attr_done = false;
    if (!attr_done) {
        cudaFuncSetAttribute(mma_gemm<0>, cudaFuncAttributeMaxDynamicSharedMemorySize, SMEM);
        cudaFuncSetAttribute(mma_gemm<1>, cudaFuncAttributeMaxDynamicSharedMemorySize, SMEM);
        cudaFuncSetAttribute(mma_gemm<2>, cudaFuncAttributeMaxDynamicSharedMemorySize, SMEM);
        cudaFuncSetAttribute(mma_gemm<3>, cudaFuncAttributeMaxDynamicSharedMemorySize, SMEM);
        attr_done = true;
    }

    const int n0 = 3*DIM*DIM/4, n1 = DIM*DIM/4, n2 = MLPH*DIM/4, n3 = DIM*MLPH/4;
    wprep_all<<<(n0+n1+n2+n3 + 255)/256, 256>>>(qkv_w, wq, n0, proj_w, wp, n1,
                                                fc1_w, w1, n2, fc2_w, w2, n3);
    tbuild_kernel<<<48, 256>>>(btab, tbl);

    // 1. LN1 + cyclic shift + window partition (half out)
    ln_kernel<1><<<ROWS, 128>>>(x, n1w, n1b, xw);
    // 2. QKV projection (fp16 tensor cores)
    mma_gemm<0><<<dim3((3*DIM)/128, ROWS/128), 128, SMEM>>>(xw, wq, qkv_b, nullptr, qkvb, ROWS, 3*DIM, DIM);
    // 3. windowed attention (fp16 tensor cores)
    attn_mma<<<dim3(BATCH*NWIN, HEADS), 128>>>(qkvb, tbl, att);
    // 4. proj + window reverse + unshift + shortcut residual (f32 out)
    mma_gemm<3><<<dim3(DIM/128, ROWS/128), 128, SMEM>>>(att, wp, proj_b, x, x1, ROWS, DIM, DIM);
    // 5. LN2 (half out)
    ln_kernel<0><<<ROWS, 128>>>(x1, n2w, n2b, z);
    // 6. fc1 + exact GELU (half out)
    mma_gemm<1><<<dim3(MLPH/128, ROWS/128), 128, SMEM>>>(z, w1, fc1_b, nullptr, hid, ROWS, MLPH, DIM);
    // 7. fc2 + residual -> final output (f32)
    mma_gemm<2><<<dim3(DIM/128, ROWS/128), 128, SMEM>>>(hid, w2, fc2_b, x1, out, ROWS, DIM, MLPH);
}

// round 9
// speedup vs baseline: 7.8548x; 1.0049x over previous
#include <cuda_runtime.h>
#include <cuda_fp16.h>
#include <math.h>
#include <stdint.h>

#define BATCH   64
#define HIMG    28
#define WIMG    28
#define DIM     384
#define HEADS   12
#define HD      32
#define WIN     7
#define SHIFT   3
#define NTOK    49
#define NWIN    16
#define ROWS    (BATCH*NWIN*NTOK)   // 50176
#define MLPH    1536

// ---------------- scratch ----------------------------------------------------
__device__ __half g_xw [ROWS*DIM];
__device__ __half g_qkv[ROWS*3*DIM];
__device__ __half g_att[ROWS*DIM];
__device__ float  g_x1 [ROWS*DIM];
__device__ __half g_z  [ROWS*DIM];
__device__ __half g_hid[(size_t)ROWS*MLPH];
// fp16 weights
__device__ __half g_wq[3*DIM*DIM];
__device__ __half g_wp[DIM*DIM];
__device__ __half g_w1[MLPH*DIM];
__device__ __half g_w2[DIM*MLPH];
// combined bias+mask table: [4 window types][12 heads][49][49]
__device__ float g_tbl[48*NTOK*NTOK];

// ---------------- helpers ------------------------------------------------------
__device__ __forceinline__ uint32_t smem_u32(const void* p) {
    uint32_t a;
    asm("{ .reg .u64 t; cvta.to.shared.u64 t, %1; cvt.u32.u64 %0, t; }" : "=r"(a) : "l"(p));
    return a;
}
__device__ __forceinline__ void cp16(uint32_t s, const void* g) {
    asm volatile("cp.async.cg.shared.global [%0], [%1], 16;" :: "r"(s), "l"(g));
}
#define CP_COMMIT() asm volatile("cp.async.commit_group;" ::: "memory")
#define CP_WAIT1()  asm volatile("cp.async.wait_group 1;" ::: "memory")

__device__ __forceinline__ void mma_f16(float* d, const uint32_t* a, const uint32_t* b) {
    asm volatile(
        "mma.sync.aligned.m16n8k16.row.col.f32.f16.f16.f32 "
        "{%0,%1,%2,%3}, {%4,%5,%6,%7}, {%8,%9}, {%0,%1,%2,%3};"
        : "+f"(d[0]), "+f"(d[1]), "+f"(d[2]), "+f"(d[3])
        : "r"(a[0]), "r"(a[1]), "r"(a[2]), "r"(a[3]), "r"(b[0]), "r"(b[1]));
}
__device__ __forceinline__ void ldsm4(uint32_t& r0, uint32_t& r1, uint32_t& r2,
                                      uint32_t& r3, uint32_t addr) {
    asm volatile("ldmatrix.sync.aligned.m8n8.x4.shared.b16 {%0,%1,%2,%3}, [%4];"
        : "=r"(r0), "=r"(r1), "=r"(r2), "=r"(r3) : "r"(addr));
}

// ---------------- weight prep: fp32 -> fp16 (all 4 matrices, 1 launch) ---------
__global__ void wprep_all(const float* s0, __half* d0, int n0,
                          const float* s1, __half* d1, int n1,
                          const float* s2, __half* d2, int n2,
                          const float* s3, __half* d3, int n3) {
    int i = blockIdx.x * blockDim.x + threadIdx.x;
    const float* s; __half* d; int j = i;
    if (j < n0) { s = s0; d = d0; }
    else { j -= n0; if (j < n1) { s = s1; d = d1; }
    else { j -= n1; if (j < n2) { s = s2; d = d2; }
    else { j -= n2; if (j >= n3) return; s = s3; d = d3; } } }
    float4 v = ((const float4*)s)[j];
    __half2* dp = (__half2*)(d + j*4);
    dp[0] = __floats2half2_rn(v.x, v.y);
    dp[1] = __floats2half2_rn(v.z, v.w);
}

// ---------------- bias+mask table build ----------------------------------------
__global__ void tbuild_kernel(const float* __restrict__ btab, float* __restrict__ tbl) {
    int th = blockIdx.x;
    int type = th / HEADS, h = th % HEADS;
    int eh = (type >> 1) & 1, ew = type & 1;
    for (int e = threadIdx.x; e < NTOK*NTOK; e += blockDim.x) {
        int n = e / NTOK, m = e % NTOK;
        int i1 = n/7, j1 = n%7, i2 = m/7, j2 = m%7;
        float v = btab[((i1 - i2 + 6)*13 + (j1 - j2 + 6))*HEADS + h];
        int r1 = (eh ? (i1 < 4 ? 1 : 2) : 0) * 3 + (ew ? (j1 < 4 ? 1 : 2) : 0);
        int r2 = (eh ? (i2 < 4 ? 1 : 2) : 0) * 3 + (ew ? (j2 < 4 ? 1 : 2) : 0);
        if (r1 != r2) v -= 100.f;
        tbl[th*NTOK*NTOK + e] = v;
    }
}

// ---------------- LayerNorm (optionally fused shift+window gather), half out ---
template<int GATHER>
__global__ void ln_kernel(const float* __restrict__ x, const float* __restrict__ w,
                          const float* __restrict__ b, __half* __restrict__ out) {
    int r = blockIdx.x;
    int src = r;
    if (GATHER) {
        int bb  = r / (NWIN*NTOK);
        int rem = r % (NWIN*NTOK);
        int win = rem / NTOK, n = rem % NTOK;
        int wh = win / 4, ww = win % 4;
        int i = n / 7, j = n % 7;
        int sh = (wh*7 + i + SHIFT) % HIMG;
        int sw = (ww*7 + j + SHIFT) % WIMG;
        src = bb*(HIMG*WIMG) + sh*WIMG + sw;
    }
    const float* xp = x + (size_t)src * DIM;
    int tid = threadIdx.x;
    float v0 = xp[tid], v1 = xp[tid+128], v2 = xp[tid+256];
    float s = v0 + v1 + v2;
    __shared__ float red[4];
    #pragma unroll
    for (int o = 16; o; o >>= 1) s += __shfl_xor_sync(~0u, s, o);
    if ((tid & 31) == 0) red[tid >> 5] = s;
    __syncthreads();
    float mean = (red[0]+red[1]+red[2]+red[3]) * (1.0f/DIM);
    float d0 = v0-mean, d1 = v1-mean, d2 = v2-mean;
    float q = d0*d0 + d1*d1 + d2*d2;
    #pragma unroll
    for (int o = 16; o; o >>= 1) q += __shfl_xor_sync(~0u, q, o);
    __syncthreads();
    if ((tid & 31) == 0) red[tid >> 5] = q;
    __syncthreads();
    float var = (red[0]+red[1]+red[2]+red[3]) * (1.0f/DIM);
    float inv = rsqrtf(var + 1e-5f);
    __half* op = out + (size_t)r * DIM;
    op[tid]     = __float2half_rn(d0*inv*w[tid]     + b[tid]);
    op[tid+128] = __float2half_rn(d1*inv*w[tid+128] + b[tid+128]);
    op[tid+256] = __float2half_rn(d2*inv*w[tid+256] + b[tid+256]);
}

// ---------------- pipelined fp16 GEMM, 4 warps, 64x64 warp tile, ldmatrix ------
// CTA tile 128x128, BK=64 halves (128B/row), 3-stage cp.async, 1 sync per tile.
#define SSZ 8192   // u32 per stage (A 4096 + B 4096)
template<int MODE>
__global__ void __launch_bounds__(128, 2)
mma_gemm(const __half* __restrict__ A, const __half* __restrict__ W,
         const float* __restrict__ bias, const float* __restrict__ res,
         void* __restrict__ outv, int M, int N, int K) {
    extern __shared__ __align__(16) uint32_t smem[];
    uint32_t sbase = smem_u32(smem);
    int tid  = threadIdx.x;
    int wid  = tid >> 5, lane = tid & 31;
    int wm   = wid >> 1, wn = wid & 1;           // warp grid 2x2
    int q    = lane >> 2, c = lane & 3;
    int m0   = blockIdx.y * 128, n0 = blockIdx.x * 128;

    int sr = tid >> 3;          // staging row base
    int sc = tid & 7;           // 16B chunk along k

    // ldmatrix per-lane geometry: row-in-16 and chunk half
    int lrow = (lane & 7) + ((lane >> 3) & 1) * 8;   // 0..15
    int lch  = lane >> 4;                            // 0 or 1
    int lb7  = lane & 7;

    const __half* Ag0 = A + (size_t)(m0 + sr) * K + sc*8;
    const __half* Wg0 = W + (size_t)(n0 + sr) * K + sc*8;

    float acc[4][8][4];
    #pragma unroll
    for (int i = 0; i < 4; i++)
        #pragma unroll
        for (int j = 0; j < 8; j++)
            #pragma unroll
            for (int e = 0; e < 4; e++) acc[i][j][e] = 0.f;

    const int T = K >> 6;       // BK = 64 halves

    auto load_tile = [&](int t) {
        uint32_t sb = sbase + (uint32_t)(t % 3) * (SSZ*4);
        const __half* Ag = Ag0 + t*64;
        const __half* Wg = Wg0 + t*64;
        #pragma unroll
        for (int i = 0; i < 8; i++) {
            int m = sr + i*16;
            uint32_t off = (uint32_t)(m*128 + ((sc*16) ^ ((m & 7) * 16)));
            cp16(sb + off,         Ag + (size_t)i*16*K);
            cp16(sb + 16384 + off, Wg + (size_t)i*16*K);
        }
    };

    load_tile(0); CP_COMMIT();
    load_tile(1); CP_COMMIT();

    for (int t = 0; t < T; t++) {
        CP_WAIT1();
        __syncthreads();
        if (t + 2 < T) load_tile(t + 2);
        CP_COMMIT();

        uint32_t stage = sbase + (uint32_t)(t % 3) * (SSZ*4);
        uint32_t abase = stage + (uint32_t)((wm*64 + lrow) * 128);
        uint32_t bbase = stage + 16384 + (uint32_t)((wn*64 + lrow) * 128);
        #pragma unroll
        for (int ks = 0; ks < 4; ks++) {       // 4 x k16
            uint32_t sw = (uint32_t)(((ks*2 + lch) ^ lb7) * 16);
            uint32_t af[4][4];
            #pragma unroll
            for (int mi = 0; mi < 4; mi++)
                ldsm4(af[mi][0], af[mi][1], af[mi][2], af[mi][3],
                      abase + mi*2048 + sw);
            uint32_t bf[8][2];
            #pragma unroll
            for (int nb = 0; nb < 4; nb++) {
                uint32_t r0, r1, r2, r3;
                ldsm4(r0, r1, r2, r3, bbase + nb*2048 + sw);
                bf[2*nb][0]   = r0; bf[2*nb+1][0] = r1;
                bf[2*nb][1]   = r2; bf[2*nb+1][1] = r3;
            }
            #pragma unroll
            for (int mi = 0; mi < 4; mi++)
                #pragma unroll
                for (int ni = 0; ni < 8; ni++)
                    mma_f16(acc[mi][ni], af[mi], bf[ni]);
        }
    }

    // ---- epilogue ----
    #pragma unroll
    for (int mi = 0; mi < 4; mi++) {
        int r0 = m0 + wm*64 + mi*16 + q;
        int r1 = r0 + 8;
        size_t or0, or1;
        if (MODE == 3) {
            #pragma unroll
            for (int half_ = 0; half_ < 2; half_++) {
                int m = half_ ? r1 : r0;
                int bbi = m / (NWIN*NTOK);
                int rem = m % (NWIN*NTOK);
                int win = rem / NTOK, n = rem % NTOK;
                int wh = win >> 2, ww = win & 3, ii = n / 7, jj = n % 7;
                int dh = (wh*7 + ii + SHIFT) % HIMG;
                int dw = (ww*7 + jj + SHIFT) % WIMG;
                size_t o = (size_t)bbi*(HIMG*WIMG) + dh*WIMG + dw;
                if (half_) or1 = o; else or0 = o;
            }
        } else {
            or0 = (size_t)r0; or1 = (size_t)r1;
        }
        #pragma unroll
        for (int ni = 0; ni < 8; ni++) {
            int col = n0 + wn*64 + ni*8 + 2*c;
            float2 bv = *(const float2*)&bias[col];
            float v00 = acc[mi][ni][0] + bv.x, v01 = acc[mi][ni][1] + bv.y;
            float v10 = acc[mi][ni][2] + bv.x, v11 = acc[mi][ni][3] + bv.y;
            if (MODE == 1) {
                v00 = 0.5f*v00*(1.0f + erff(v00*0.70710678118654752f));
                v01 = 0.5f*v01*(1.0f + erff(v01*0.70710678118654752f));
                v10 = 0.5f*v10*(1.0f + erff(v10*0.70710678118654752f));
                v11 = 0.5f*v11*(1.0f + erff(v11*0.70710678118654752f));
            }
            if (MODE >= 2) {
                float2 ra = *(const float2*)&res[or0*N + col];
                float2 rb = *(const float2*)&res[or1*N + col];
                v00 += ra.x; v01 += ra.y; v10 += rb.x; v11 += rb.y;
            }
            if (MODE == 0 || MODE == 1) {
                __half* O = (__half*)outv;
                *(__half2*)&O[or0*N + col] = __floats2half2_rn(v00, v01);
                *(__half2*)&O[or1*N + col] = __floats2half2_rn(v10, v11);
            } else {
                float* O = (float*)outv;
                float2 o0; o0.x = v00; o0.y = v01;
                float2 o1; o1.x = v10; o1.y = v11;
                *(float2*)&O[or0*N + col] = o0;
                *(float2*)&O[or1*N + col] = o1;
            }
        }
    }
}

// ---------------- fp16 tensor-core windowed attention --------------------------
#define QS2 20
#define VS2 36
#define PS2 36
__global__ void __launch_bounds__(128)
attn_mma(const __half* __restrict__ qkv, const float* __restrict__ tbl,
         __half* __restrict__ out) {
    int bw = blockIdx.x, h = blockIdx.y;
    __shared__ uint32_t sm[6752];
    uint32_t* qs  = sm;                 // 1280
    uint32_t* kkp = sm + 1280;          // 1120
    uint32_t* vvT = sm + 2400;          // 1152
    float*    tsm = (float*)(sm + 3552);// 3200 floats
    uint32_t* ps  = sm;                 // 2304 (aliases qs+kk)
    __half* qsh = (__half*)qs;
    __half* kkh = (__half*)kkp;
    __half* vvh = (__half*)vvT;
    int tid = threadIdx.x;
    int wid = tid >> 5, lane = tid & 31;
    int q8 = lane >> 2, c4 = lane & 3;
    const float scale = 0.17677669529663689f;

    for (int idx = tid; idx < 64*32; idx += 128) {
        int n = idx >> 5, d = idx & 31;
        float qv = 0.f, kv = 0.f, vv_ = 0.f;
        if (n < NTOK) {
            size_t base = (size_t)(bw*NTOK + n)*(3*DIM) + h*HD + d;
            qv  = __half2float(qkv[base]) * scale;
            kv  = __half2float(qkv[base + DIM]);
            vv_ = __half2float(qkv[base + 2*DIM]);
        }
        qsh[n*(QS2*2) + d] = __float2half_rn(qv);
        if (n < 56) kkh[n*(QS2*2) + d] = __float2half_rn(kv);
        vvh[d*(VS2*2) + n] = __float2half_rn(vv_);
    }
    {
        int win = bw % NWIN;
        int type = ((win >> 2) == 3 ? 2 : 0) + ((win & 3) == 3 ? 1 : 0);
        const float* tp = tbl + (size_t)(type*HEADS + h)*NTOK*NTOK;
        for (int i = tid; i < NTOK*NTOK; i += 128) tsm[i] = tp[i];
    }
    __syncthreads();

    int row = wid*16 + q8;

    float s[7][4];
    #pragma unroll
    for (int nf = 0; nf < 7; nf++)
        #pragma unroll
        for (int e = 0; e < 4; e++) s[nf][e] = 0.f;
    #pragma unroll
    for (int ks = 0; ks < 2; ks++) {
        int kb = ks*8;
        uint32_t af[4];
        af[0] = qs[row*QS2 + kb + c4];
        af[1] = qs[(row+8)*QS2 + kb + c4];
        af[2] = qs[row*QS2 + kb + c4 + 4];
        af[3] = qs[(row+8)*QS2 + kb + c4 + 4];
        #pragma unroll
        for (int nf = 0; nf < 7; nf++) {
            uint32_t bf[2];
            bf[0] = kkp[(nf*8 + q8)*QS2 + kb + c4];
            bf[1] = kkp[(nf*8 + q8)*QS2 + kb + c4 + 4];
            mma_f16(s[nf], af, bf);
        }
    }
    __syncthreads();   // qs/kk dead; ps may overwrite

    bool rv0 = row < NTOK, rv1 = (row+8) < NTOK;
    float mx0 = -1e30f, mx1 = -1e30f;
    #pragma unroll
    for (int nf = 0; nf < 7; nf++) {
        int col0 = nf*8 + 2*c4, col1 = col0 + 1;
        bool cv0 = col0 < NTOK, cv1 = col1 < NTOK;
        s[nf][0] = (rv0 && cv0) ? s[nf][0] + tsm[row*NTOK + col0] : -1e30f;
        s[nf][1] = (rv0 && cv1) ? s[nf][1] + tsm[row*NTOK + col1] : -1e30f;
        s[nf][2] = (rv1 && cv0) ? s[nf][2] + tsm[(row+8)*NTOK + col0] : -1e30f;
        s[nf][3] = (rv1 && cv1) ? s[nf][3] + tsm[(row+8)*NTOK + col1] : -1e30f;
        mx0 = fmaxf(mx0, fmaxf(s[nf][0], s[nf][1]));
        mx1 = fmaxf(mx1, fmaxf(s[nf][2], s[nf][3]));
    }
    mx0 = fmaxf(mx0, __shfl_xor_sync(~0u, mx0, 1));
    mx0 = fmaxf(mx0, __shfl_xor_sync(~0u, mx0, 2));
    mx1 = fmaxf(mx1, __shfl_xor_sync(~0u, mx1, 1));
    mx1 = fmaxf(mx1, __shfl_xor_sync(~0u, mx1, 2));
    float sum0 = 0.f, sum1 = 0.f;
    #pragma unroll
    for (int nf = 0; nf < 7; nf++) {
        float e0 = __expf(s[nf][0] - mx0);
        float e1 = __expf(s[nf][1] - mx0);
        float e2 = __expf(s[nf][2] - mx1);
        float e3 = __expf(s[nf][3] - mx1);
        sum0 += e0 + e1; sum1 += e2 + e3;
        __half2 p0 = __floats2half2_rn(e0, e1);
        __half2 p1 = __floats2half2_rn(e2, e3);
        ps[row*PS2 + nf*4 + c4]     = *(uint32_t*)&p0;
        ps[(row+8)*PS2 + nf*4 + c4] = *(uint32_t*)&p1;
    }
    ps[row*PS2 + 28 + c4]     = 0;
    ps[(row+8)*PS2 + 28 + c4] = 0;
    sum0 += __shfl_xor_sync(~0u, sum0, 1);
    sum0 += __shfl_xor_sync(~0u, sum0, 2);
    sum1 += __shfl_xor_sync(~0u, sum1, 1);
    sum1 += __shfl_xor_sync(~0u, sum1, 2);
    float inv0 = 1.f / sum0, inv1 = 1.f / sum1;
    __syncwarp();

    float o[4][4];
    #pragma unroll
    for (int ni = 0; ni < 4; ni++)
        #pragma unroll
        for (int e = 0; e < 4; e++) o[ni][e] = 0.f;
    #pragma unroll
    for (int ks = 0; ks < 4; ks++) {
        int kb = ks*8;
        uint32_t af[4];
        af[0] = ps[row*PS2 + kb + c4];
        af[1] = ps[(row+8)*PS2 + kb + c4];
        af[2] = ps[row*PS2 + kb + c4 + 4];
        af[3] = ps[(row+8)*PS2 + kb + c4 + 4];
        #pragma unroll
        for (int ni = 0; ni < 4; ni++) {
            uint32_t bf[2];
            bf[0] = vvT[(ni*8 + q8)*VS2 + kb + c4];
            bf[1] = vvT[(ni*8 + q8)*VS2 + kb + c4 + 4];
            mma_f16(o[ni], af, bf);
        }
    }

    #pragma unroll
    for (int ni = 0; ni < 4; ni++) {
        int d0 = ni*8 + 2*c4;
        if (rv0) {
            __half2 hv = __floats2half2_rn(o[ni][0]*inv0, o[ni][1]*inv0);
            *(__half2*)&out[(size_t)(bw*NTOK + row)*DIM + h*HD + d0] = hv;
        }
        if (rv1) {
            __half2 hv = __floats2half2_rn(o[ni][2]*inv1, o[ni][3]*inv1);
            *(__half2*)&out[(size_t)(bw*NTOK + row + 8)*DIM + h*HD + d0] = hv;
        }
    }
}

// ---------------- launcher -----------------------------------------------------
extern "C" void kernel_launch(void* const* d_in, const int* in_sizes, int n_in,
                              void* d_out, int out_size) {
    const float* x      = (const float*)d_in[0];
    const float* n1w    = (const float*)d_in[1];
    const float* n1b    = (const float*)d_in[2];
    const float* qkv_w  = (const float*)d_in[3];
    const float* qkv_b  = (const float*)d_in[4];
    const float* proj_w = (const float*)d_in[5];
    const float* proj_b = (const float*)d_in[6];
    const float* btab   = (const float*)d_in[7];
    const float* n2w    = (const float*)d_in[8];
    const float* n2b    = (const float*)d_in[9];
    const float* fc1_w  = (const float*)d_in[10];
    const float* fc1_b  = (const float*)d_in[11];
    const float* fc2_w  = (const float*)d_in[12];
    const float* fc2_b  = (const float*)d_in[13];
    float* out = (float*)d_out;

    __half *xw, *qkvb, *att, *z, *hid, *wq, *wp, *w1, *w2;
    float *x1, *tbl;
    cudaGetSymbolAddress((void**)&xw,   g_xw);
    cudaGetSymbolAddress((void**)&qkvb, g_qkv);
    cudaGetSymbolAddress((void**)&att,  g_att);
    cudaGetSymbolAddress((void**)&x1,   g_x1);
    cudaGetSymbolAddress((void**)&z,    g_z);
    cudaGetSymbolAddress((void**)&hid,  g_hid);
    cudaGetSymbolAddress((void**)&wq,   g_wq);
    cudaGetSymbolAddress((void**)&wp,   g_wp);
    cudaGetSymbolAddress((void**)&w1,   g_w1);
    cudaGetSymbolAddress((void**)&w2,   g_w2);
    cudaGetSymbolAddress((void**)&tbl,  g_tbl);

    const int SMEM = 3 * SSZ * 4;   // 98304 bytes
    static bool attr_done = false;
    if (!attr_done) {
        cudaFuncSetAttribute(mma_gemm<0>, cudaFuncAttributeMaxDynamicSharedMemorySize, SMEM);
        cudaFuncSetAttribute(mma_gemm<1>, cudaFuncAttributeMaxDynamicSharedMemorySize, SMEM);
        cudaFuncSetAttribute(mma_gemm<2>, cudaFuncAttributeMaxDynamicSharedMemorySize, SMEM);
        cudaFuncSetAttribute(mma_gemm<3>, cudaFuncAttributeMaxDynamicSharedMemorySize, SMEM);
        attr_done = true;
    }

    const int n0 = 3*DIM*DIM/4, n1 = DIM*DIM/4, n2 = MLPH*DIM/4, n3 = DIM*MLPH/4;
    wprep_all<<<(n0+n1+n2+n3 + 255)/256, 256>>>(qkv_w, wq, n0, proj_w, wp, n1,
                                                fc1_w, w1, n2, fc2_w, w2, n3);
    tbuild_kernel<<<48, 256>>>(btab, tbl);

    // 1. LN1 + cyclic shift + window partition (half out)
    ln_kernel<1><<<ROWS, 128>>>(x, n1w, n1b, xw);
    // 2. QKV projection (fp16 tensor cores, ldmatrix)
    mma_gemm<0><<<dim3((3*DIM)/128, ROWS/128), 128, SMEM>>>(xw, wq, qkv_b, nullptr, qkvb, ROWS, 3*DIM, DIM);
    // 3. windowed attention (fp16 tensor cores)
    attn_mma<<<dim3(BATCH*NWIN, HEADS), 128>>>(qkvb, tbl, att);
    // 4. proj + window reverse + unshift + shortcut residual (f32 out)
    mma_gemm<3><<<dim3(DIM/128, ROWS/128), 128, SMEM>>>(att, wp, proj_b, x, x1, ROWS, DIM, DIM);
    // 5. LN2 (half out)
    ln_kernel<0><<<ROWS, 128>>>(x1, n2w, n2b, z);
    // 6. fc1 + exact GELU (half out)
    mma_gemm<1><<<dim3(MLPH/128, ROWS/128), 128, SMEM>>>(z, w1, fc1_b, nullptr, hid, ROWS, MLPH, DIM);
    // 7. fc2 + residual -> final output (f32)
    mma_gemm<2><<<dim3(DIM/128, ROWS/128), 128, SMEM>>>(hid, w2, fc2_b, x1, out, ROWS, DIM, MLPH);
}